// round 11
// baseline (speedup 1.0000x reference)
#include <cuda_runtime.h>
#include <cuda_fp16.h>
#include <math.h>
#include <stdint.h>

// Problem dims
#define LYR 3
#define HH  8
#define DD  128
#define DKK 16
#define FF  512
#define BB  32
#define NN  512
#define FIN 16
#define OUTD 3
#define ROWS (BB*NN)          // 16384
#define QKVN (3*DD)           // 384
#define SCL (0.25f * 1.44269504089f)
#define MASKVAL (-2e30f)
#define MINIT   (-1e30f)

// prep segment sizes
#define N_XH   (ROWS*FIN)
#define N_WE   (FIN*DD)
#define N_QKV  (LYR*QKVN*DD)
#define N_WOUT (LYR*DD*DD)
#define N_FF1  (LYR*FF*DD)
#define N_FF2  (LYR*DD*FF)
#define N_PREP (N_XH+N_WE+N_QKV+N_WOUT+N_FF1+N_FF2)

// ---------------- scratch (__device__ globals; no allocation) ----------------
__device__ __align__(16) float  g_h[ROWS*DD];       // exact fp32 trunk
__device__ __align__(16) __half g_hh[ROWS*DD];      // fp16 trunk copy
__device__ __align__(16) __half g_qkv[ROWS*QKVN];   // Q section pre-scaled by SCL
__device__ __align__(16) __half g_heads[ROWS*DD];
__device__ __align__(16) __half g_ff[ROWS*FF];
__device__ __align__(16) __half g_xh[ROWS*FIN];
__device__ __align__(16) float  g_hpp[BB*DD];
__device__ __align__(16) unsigned g_mpack[BB*NN*(NN/32)];
// transposed fp16 weights [N][K]
__device__ __align__(16) __half g_weT[DD*FIN];
__device__ __align__(16) __half g_wqkvT[LYR*QKVN*DD];
__device__ __align__(16) __half g_woutT[LYR*DD*DD];
__device__ __align__(16) __half g_wff1T[LYR*FF*DD];
__device__ __align__(16) __half g_wff2T[LYR*DD*FF];

// ---------------- helpers ----------------------------------------------------
__device__ __forceinline__ uint32_t smem_u32(const void* p){
    uint32_t a;
    asm("{ .reg .u64 t; cvta.to.shared.u64 t, %1; cvt.u32.u64 %0, t; }" : "=r"(a) : "l"(p));
    return a;
}
__device__ __forceinline__ void cpa16(uint32_t s, const void* g){
    asm volatile("cp.async.cg.shared.global [%0], [%1], 16;" :: "r"(s), "l"(g) : "memory");
}
__device__ __forceinline__ void ldsm4(uint32_t& r0, uint32_t& r1, uint32_t& r2, uint32_t& r3,
                                      uint32_t addr){
    asm volatile("ldmatrix.sync.aligned.m8n8.x4.shared.b16 {%0,%1,%2,%3}, [%4];"
                 : "=r"(r0), "=r"(r1), "=r"(r2), "=r"(r3) : "r"(addr));
}
__device__ __forceinline__ void ldsm4t(uint32_t& r0, uint32_t& r1, uint32_t& r2, uint32_t& r3,
                                       uint32_t addr){
    asm volatile("ldmatrix.sync.aligned.m8n8.x4.trans.shared.b16 {%0,%1,%2,%3}, [%4];"
                 : "=r"(r0), "=r"(r1), "=r"(r2), "=r"(r3) : "r"(addr));
}
__device__ __forceinline__ void mma_f16(float c[4], const uint32_t a[4],
                                        uint32_t b0, uint32_t b1){
    asm volatile("mma.sync.aligned.m16n8k16.row.col.f32.f16.f16.f32 "
        "{%0,%1,%2,%3},{%4,%5,%6,%7},{%8,%9},{%0,%1,%2,%3};\n"
        : "+f"(c[0]),"+f"(c[1]),"+f"(c[2]),"+f"(c[3])
        : "r"(a[0]),"r"(a[1]),"r"(a[2]),"r"(a[3]),"r"(b0),"r"(b1));
}
__device__ __forceinline__ uint32_t f16x2(float hi, float lo){
    uint32_t r; asm("cvt.rn.f16x2.f32 %0, %1, %2;" : "=r"(r) : "f"(hi), "f"(lo));
    return r;
}

// ---------------- fused prep --------------------------------------------------
__global__ void prep_all(const float* __restrict__ x,   const float* __restrict__ We,
                         const float* __restrict__ Wq,  const float* __restrict__ Wk,
                         const float* __restrict__ Wv,  const float* __restrict__ Wout,
                         const float* __restrict__ Wff1,const float* __restrict__ Wff2,
                         __half* __restrict__ xh,   __half* __restrict__ weT,
                         __half* __restrict__ wqkvT,__half* __restrict__ woutT,
                         __half* __restrict__ wff1T,__half* __restrict__ wff2T)
{
    int idx = blockIdx.x * 256 + threadIdx.x;
    if (idx < N_XH){ xh[idx] = __float2half_rn(x[idx]); return; }
    idx -= N_XH;
    if (idx < N_WE){
        int cc = idx / FIN, rr = idx % FIN;
        weT[idx] = __float2half_rn(We[rr * DD + cc]); return;
    }
    idx -= N_WE;
    if (idx < N_QKV){
        int l = idx / (QKVN*DD), rem = idx % (QKVN*DD);
        int n = rem / DD, d = rem % DD;
        int sel = n >> 7, hc = n & 127, h2 = hc >> 4, kk = hc & 15;
        const float* W = (sel == 0) ? Wq : (sel == 1) ? Wk : Wv;
        wqkvT[idx] = __float2half_rn(W[(((l*HH + h2)*DD) + d)*DKK + kk]); return;
    }
    idx -= N_QKV;
    if (idx < N_WOUT){
        int l = idx / (DD*DD), rem = idx % (DD*DD);
        int cc = rem / DD, rr = rem % DD;
        woutT[idx] = __float2half_rn(Wout[(size_t)l*DD*DD + rr*DD + cc]); return;
    }
    idx -= N_WOUT;
    if (idx < N_FF1){
        int l = idx / (FF*DD), rem = idx % (FF*DD);
        int cc = rem / DD, rr = rem % DD;
        wff1T[idx] = __float2half_rn(Wff1[(size_t)l*DD*FF + rr*FF + cc]); return;
    }
    idx -= N_FF1;
    if (idx < N_FF2){
        int l = idx / (DD*FF), rem = idx % (DD*FF);
        int cc = rem / FF, rr = rem % FF;
        wff2T[idx] = __float2half_rn(Wff2[(size_t)l*FF*DD + rr*DD + cc]); return;
    }
}

__global__ void maskpack_kernel(const int* __restrict__ mask, unsigned* __restrict__ mpack){
    int idx = blockIdx.x * 256 + threadIdx.x;
    if (idx >= BB*NN*(NN/32)) return;
    const int* src = mask + (size_t)idx * 32;
    unsigned v = 0;
#pragma unroll
    for (int j = 0; j < 32; j += 4){
        int4 mm = *(const int4*)(src + j);
        v |= ((unsigned)(mm.x != 0)) << (j    );
        v |= ((unsigned)(mm.y != 0)) << (j + 1);
        v |= ((unsigned)(mm.z != 0)) << (j + 2);
        v |= ((unsigned)(mm.w != 0)) << (j + 3);
    }
    mpack[idx] = v;
}

// ---------------- streaming fp16 tensor GEMM, small CTA ----------------------
// BM=64, BN=64, 128 threads = 4 warps (2m x 2n), warp tile 32x32 (same per-warp
// stream as the proven kernel). cp.async 3-stage. High CTA count -> high occ.
template<int BK>
__global__ __launch_bounds__(128)
void gemm_hc(const __half* __restrict__ A, const __half* __restrict__ Bt,
             const float* __restrict__ bias, const float* __restrict__ res,
             float* __restrict__ C, __half* __restrict__ Ch,
             int M, int K, int N, int do_relu, int scaleq)
{
    constexpr int BM = 64, BN = 64, S = 3, THR = 128;
    constexpr int CH = BK / 8;
    constexpr int PB = BK * 2 + 16;
    constexpr int ABYTES = BM * PB, BBYTES = BN * PB;
    constexpr int STAGE = ABYTES + BBYTES;
    constexpr int ACH = BM * CH, BCH = BN * CH;
    constexpr int KS = BK / 16;

    extern __shared__ char smraw[];
    const uint32_t smbase = smem_u32(smraw);

    const int tid = threadIdx.x, lane = tid & 31, wid = tid >> 5;
    const int wm = wid >> 1, wn = wid & 1;          // 2x2 warps
    const int brow = blockIdx.y * BM, bcol = blockIdx.x * BN;
    const int ntile = K / BK;

    float c[2][4][4];
#pragma unroll
    for (int mt = 0; mt < 2; mt++)
#pragma unroll
        for (int nt = 0; nt < 4; nt++)
#pragma unroll
            for (int i = 0; i < 4; i++) c[mt][nt][i] = 0.f;

#pragma unroll
    for (int s = 0; s < S - 1; s++){
        if (s < ntile){
            uint32_t sb = smbase + s * STAGE;
#pragma unroll
            for (int j = 0; j < (ACH + THR - 1)/THR; j++){
                int id = tid + j * THR;
                if ((ACH % THR) == 0 || id < ACH){
                    int r = id / CH, cc = id % CH;
                    cpa16(sb + r * PB + cc * 16,
                          A + (size_t)(brow + r) * K + s * BK + cc * 8);
                }
            }
#pragma unroll
            for (int j = 0; j < (BCH + THR - 1)/THR; j++){
                int id = tid + j * THR;
                if ((BCH % THR) == 0 || id < BCH){
                    int r = id / CH, cc = id % CH;
                    cpa16(sb + ABYTES + r * PB + cc * 16,
                          Bt + (size_t)(bcol + r) * K + s * BK + cc * 8);
                }
            }
        }
        asm volatile("cp.async.commit_group;" ::: "memory");
    }

    const int arow0 = wm * 32 + (lane & 15);
    const int ahi = lane >> 4;
    const int bhi = (lane >> 3) & 1;
    const int brfrag = wn * 32 + (lane & 7) + ((lane >> 4) << 3);

    for (int t = 0; t < ntile; t++){
        asm volatile("cp.async.wait_group %0;" :: "n"(S - 2) : "memory");
        __syncthreads();

        {
            int tn = t + S - 1;
            if (tn < ntile){
                uint32_t sb = smbase + (tn % S) * STAGE;
#pragma unroll
                for (int j = 0; j < (ACH + THR - 1)/THR; j++){
                    int id = tid + j * THR;
                    if ((ACH % THR) == 0 || id < ACH){
                        int r = id / CH, cc = id % CH;
                        cpa16(sb + r * PB + cc * 16,
                              A + (size_t)(brow + r) * K + tn * BK + cc * 8);
                    }
                }
#pragma unroll
                for (int j = 0; j < (BCH + THR - 1)/THR; j++){
                    int id = tid + j * THR;
                    if ((BCH % THR) == 0 || id < BCH){
                        int r = id / CH, cc = id % CH;
                        cpa16(sb + ABYTES + r * PB + cc * 16,
                              Bt + (size_t)(bcol + r) * K + tn * BK + cc * 8);
                    }
                }
            }
            asm volatile("cp.async.commit_group;" ::: "memory");
        }

        uint32_t sb = smbase + (t % S) * STAGE;
#pragma unroll
        for (int ks = 0; ks < KS; ks++){
            uint32_t af[2][4];
#pragma unroll
            for (int mt = 0; mt < 2; mt++){
                int r = arow0 + mt * 16;
                ldsm4(af[mt][0], af[mt][1], af[mt][2], af[mt][3],
                      sb + r * PB + (ks * 2 + ahi) * 16);
            }
            uint32_t bf[2][4];
#pragma unroll
            for (int pr = 0; pr < 2; pr++){
                int r = brfrag + pr * 16;
                ldsm4(bf[pr][0], bf[pr][1], bf[pr][2], bf[pr][3],
                      sb + ABYTES + r * PB + (ks * 2 + bhi) * 16);
            }
#pragma unroll
            for (int mt = 0; mt < 2; mt++)
#pragma unroll
                for (int pr = 0; pr < 2; pr++){
                    mma_f16(c[mt][2*pr],     af[mt], bf[pr][0], bf[pr][1]);
                    mma_f16(c[mt][2*pr + 1], af[mt], bf[pr][2], bf[pr][3]);
                }
        }
    }

    // ---- epilogue ----
#pragma unroll
    for (int mt = 0; mt < 2; mt++){
        int r0 = brow + wm * 32 + mt * 16 + (lane >> 2);
#pragma unroll
        for (int nt = 0; nt < 4; nt++){
            int col = bcol + wn * 32 + nt * 8 + (lane & 3) * 2;
            float2 bb = make_float2(0.f, 0.f);
            if (bias) bb = *(const float2*)(bias + col);
            size_t off0 = (size_t)r0 * N + col;
            size_t off1 = (size_t)(r0 + 8) * N + col;
            float2 v0 = make_float2(c[mt][nt][0] + bb.x, c[mt][nt][1] + bb.y);
            float2 v1 = make_float2(c[mt][nt][2] + bb.x, c[mt][nt][3] + bb.y);
            if (res){
                float2 r0v = *(const float2*)(res + off0);
                float2 r1v = *(const float2*)(res + off1);
                v0.x += r0v.x; v0.y += r0v.y; v1.x += r1v.x; v1.y += r1v.y;
            }
            if (do_relu){
                v0.x = fmaxf(v0.x, 0.f); v0.y = fmaxf(v0.y, 0.f);
                v1.x = fmaxf(v1.x, 0.f); v1.y = fmaxf(v1.y, 0.f);
            }
            if (scaleq && col < DD){
                v0.x *= SCL; v0.y *= SCL; v1.x *= SCL; v1.y *= SCL;
            }
            if (C){
                *(float2*)(C + off0) = v0;
                *(float2*)(C + off1) = v1;
            }
            if (Ch){
                *(__half2*)(Ch + off0) = __floats2half2_rn(v0.x, v0.y);
                *(__half2*)(Ch + off1) = __floats2half2_rn(v1.x, v1.y);
            }
        }
    }
}

// ---------------- flash attention, all-fp16 MMA (Q pre-scaled) ---------------
#define KS_BYTES (NN*48)
#define ATTN_SMEM (2*KS_BYTES)

__global__ __launch_bounds__(256)
void attn_mma(const __half* __restrict__ qkv, const unsigned* __restrict__ mpack,
              __half* __restrict__ heads)
{
    extern __shared__ char smraw[];
    const uint32_t ksbase = smem_u32(smraw);
    const uint32_t vsbase = ksbase + KS_BYTES;

    const int b = blockIdx.x >> 3, h = blockIdx.x & 7;
    const int tid = threadIdx.x, lane = tid & 31, wid = tid >> 5;

    for (int i = tid; i < NN * 2; i += 256){
        int row = i >> 1, cc = i & 1;
        const __half* base = qkv + (size_t)(b * NN + row) * QKVN + h * DKK;
        *(uint4*)(smraw + row * 48 + cc * 16) = *(const uint4*)(base + DD + cc * 8);
        *(uint4*)(smraw + KS_BYTES + row * 48 + cc * 16) =
            *(const uint4*)(base + 2 * DD + cc * 8);
    }
    __syncthreads();

    const __half* Qb = qkv + (size_t)(b * NN) * QKVN + h * DKK;
    const int bfr = (lane & 7) + ((lane >> 4) << 3);
    const int bhi = (lane >> 3) & 1;
    const int vcol = (lane >> 4) << 4;

    for (int qb = 0; qb < 4; qb++){
        const int qrow = qb * 128 + wid * 16 + (lane >> 2);

        uint32_t aq[4];
        {
            const __half* q0 = Qb + (size_t)qrow * QKVN + (lane & 3) * 2;
            const __half* q1 = Qb + (size_t)(qrow + 8) * QKVN + (lane & 3) * 2;
            aq[0] = *(const uint32_t*)q0;
            aq[1] = *(const uint32_t*)q1;
            aq[2] = *(const uint32_t*)(q0 + 8);
            aq[3] = *(const uint32_t*)(q1 + 8);
        }

        float m0 = MINIT, m1 = MINIT, l0 = 0.f, l1 = 0.f;
        float o[2][4];
#pragma unroll
        for (int vt = 0; vt < 2; vt++)
#pragma unroll
            for (int i = 0; i < 4; i++) o[vt][i] = 0.f;

        for (int kb = 0; kb < 8; kb++){
            float s[8][4];
#pragma unroll
            for (int nt = 0; nt < 8; nt++)
                s[nt][0] = s[nt][1] = s[nt][2] = s[nt][3] = 0.f;
#pragma unroll
            for (int pr = 0; pr < 4; pr++){
                int rn = kb * 64 + pr * 16 + bfr;
                uint32_t b0, b1, b2, b3;
                ldsm4(b0, b1, b2, b3, ksbase + rn * 48 + bhi * 16);
                mma_f16(s[2*pr],     aq, b0, b1);
                mma_f16(s[2*pr + 1], aq, b2, b3);
            }
            // mask (Q already carries SCL)
            const unsigned* mpr = mpack + ((size_t)(b * NN + qrow) << 4) + kb * 2;
            unsigned mw00 = mpr[0], mw01 = mpr[1];
            unsigned mw10 = mpr[8 * 16], mw11 = mpr[8 * 16 + 1];
#pragma unroll
            for (int nt = 0; nt < 8; nt++){
                int cb = nt * 8 + (lane & 3) * 2;
                unsigned wlo = (cb & 32) ? mw01 : mw00;
                unsigned whi = (cb & 32) ? mw11 : mw10;
                int bit = cb & 31;
                s[nt][0] = ((wlo >> bit)       & 1) ? s[nt][0] : MASKVAL;
                s[nt][1] = ((wlo >> (bit + 1)) & 1) ? s[nt][1] : MASKVAL;
                s[nt][2] = ((whi >> bit)       & 1) ? s[nt][2] : MASKVAL;
                s[nt][3] = ((whi >> (bit + 1)) & 1) ? s[nt][3] : MASKVAL;
            }
            // online softmax (log2 domain)
            float rx0 = MASKVAL, rx1 = MASKVAL;
#pragma unroll
            for (int nt = 0; nt < 8; nt++){
                rx0 = fmaxf(rx0, fmaxf(s[nt][0], s[nt][1]));
                rx1 = fmaxf(rx1, fmaxf(s[nt][2], s[nt][3]));
            }
            rx0 = fmaxf(rx0, __shfl_xor_sync(0xffffffffu, rx0, 1));
            rx0 = fmaxf(rx0, __shfl_xor_sync(0xffffffffu, rx0, 2));
            rx1 = fmaxf(rx1, __shfl_xor_sync(0xffffffffu, rx1, 1));
            rx1 = fmaxf(rx1, __shfl_xor_sync(0xffffffffu, rx1, 2));
            float nm0 = fmaxf(m0, rx0), nm1 = fmaxf(m1, rx1);
            float f0 = exp2f(m0 - nm0), f1 = exp2f(m1 - nm1);
            m0 = nm0; m1 = nm1;
            l0 *= f0;  l1 *= f1;
#pragma unroll
            for (int vt = 0; vt < 2; vt++){
                o[vt][0] *= f0; o[vt][1] *= f0;
                o[vt][2] *= f1; o[vt][3] *= f1;
            }
#pragma unroll
            for (int nt = 0; nt < 8; nt++){
                s[nt][0] = exp2f(s[nt][0] - m0);
                s[nt][1] = exp2f(s[nt][1] - m0);
                s[nt][2] = exp2f(s[nt][2] - m1);
                s[nt][3] = exp2f(s[nt][3] - m1);
                l0 += s[nt][0] + s[nt][1];
                l1 += s[nt][2] + s[nt][3];
            }
            // P @ V
#pragma unroll
            for (int kt = 0; kt < 4; kt++){
                uint32_t pa[4];
                pa[0] = f16x2(s[2 * kt][1],     s[2 * kt][0]);
                pa[1] = f16x2(s[2 * kt][3],     s[2 * kt][2]);
                pa[2] = f16x2(s[2 * kt + 1][1], s[2 * kt + 1][0]);
                pa[3] = f16x2(s[2 * kt + 1][3], s[2 * kt + 1][2]);
                int rv = kb * 64 + kt * 16 + (lane & 15);
                uint32_t vb0, vb1, vb2, vb3;
                ldsm4t(vb0, vb1, vb2, vb3, vsbase + rv * 48 + vcol);
                mma_f16(o[0], pa, vb0, vb1);
                mma_f16(o[1], pa, vb2, vb3);
            }
        }

        l0 += __shfl_xor_sync(0xffffffffu, l0, 1);
        l0 += __shfl_xor_sync(0xffffffffu, l0, 2);
        l1 += __shfl_xor_sync(0xffffffffu, l1, 1);
        l1 += __shfl_xor_sync(0xffffffffu, l1, 2);
        float i0 = 1.f / l0, i1 = 1.f / l1;
#pragma unroll
        for (int vt = 0; vt < 2; vt++){
            int col = h * DKK + vt * 8 + (lane & 3) * 2;
            *(__half2*)&heads[(size_t)(b * NN + qrow) * DD + col] =
                __floats2half2_rn(o[vt][0] * i0, o[vt][1] * i0);
            *(__half2*)&heads[(size_t)(b * NN + qrow + 8) * DD + col] =
                __floats2half2_rn(o[vt][2] * i1, o[vt][3] * i1);
        }
    }
}

// ---------------- pooling + Wp ------------------------------------------------
__global__ void pool_kernel(const float* __restrict__ h, const float* __restrict__ Wp,
                            float* __restrict__ hpp)
{
    __shared__ float mean[DD];
    int b = blockIdx.x, d = threadIdx.x;
    const float* hp = h + (size_t)b * NN * DD + d;
    float s = 0.f;
    for (int n = 0; n < NN; n++) s += hp[(size_t)n * DD];
    mean[d] = s * (1.f / (float)NN);
    __syncthreads();
    float acc = 0.f;
#pragma unroll 4
    for (int i = 0; i < DD; i++) acc += mean[i] * Wp[i * DD + d];
    hpp[b * DD + d] = acc;
}

// ---------------- readout ----------------------------------------------------
__global__ void readout_kernel(const float* __restrict__ h, const float* __restrict__ hpp,
                               const float* __restrict__ Wr, const float* __restrict__ br,
                               float* __restrict__ out)
{
    __shared__ float WrS[2 * DD * OUTD];
    __shared__ float brS[OUTD];
    int tid = threadIdx.x;
    for (int i = tid; i < 2 * DD * OUTD; i += 128) WrS[i] = Wr[i];
    if (tid < OUTD) brS[tid] = br[tid];
    __syncthreads();

    int row = blockIdx.x * 128 + tid;
    int b = row >> 9;
    float a0 = brS[0], a1 = brS[1], a2 = brS[2];
    const float* hp = hpp + b * DD;
#pragma unroll 4
    for (int i = 0; i < DD; i++){
        float f = fmaxf(hp[i], 0.f);
        a0 += f * WrS[i * 3 + 0]; a1 += f * WrS[i * 3 + 1]; a2 += f * WrS[i * 3 + 2];
    }
    const float* hr = h + (size_t)row * DD;
#pragma unroll 4
    for (int i = 0; i < DD; i++){
        float f = fmaxf(hr[i], 0.f);
        a0 += f * WrS[(DD + i) * 3 + 0];
        a1 += f * WrS[(DD + i) * 3 + 1];
        a2 += f * WrS[(DD + i) * 3 + 2];
    }
    out[row * 3 + 0] = a0; out[row * 3 + 1] = a1; out[row * 3 + 2] = a2;
}

// ---------------- host launcher ----------------------------------------------
extern "C" void kernel_launch(void* const* d_in, const int* in_sizes, int n_in,
                              void* d_out, int out_size)
{
    const float* x    = (const float*)d_in[0];
    const int*   mask = (const int*)  d_in[1];
    const float* We   = (const float*)d_in[2];
    const float* Wq   = (const float*)d_in[3];
    const float* Wk   = (const float*)d_in[4];
    const float* Wv   = (const float*)d_in[5];
    const float* Wout = (const float*)d_in[6];
    const float* Wff1 = (const float*)d_in[7];
    const float* bff1 = (const float*)d_in[8];
    const float* Wff2 = (const float*)d_in[9];
    const float* bff2 = (const float*)d_in[10];
    const float* Wp   = (const float*)d_in[11];
    const float* Wr   = (const float*)d_in[12];
    const float* br   = (const float*)d_in[13];
    float* out = (float*)d_out;

    float *h, *hpp;
    __half *hh, *qkv, *heads, *ff, *xh, *weT, *wqkvT, *woutT, *wff1T, *wff2T;
    unsigned* mp;
    cudaGetSymbolAddress((void**)&h,     g_h);
    cudaGetSymbolAddress((void**)&hh,    g_hh);
    cudaGetSymbolAddress((void**)&qkv,   g_qkv);
    cudaGetSymbolAddress((void**)&heads, g_heads);
    cudaGetSymbolAddress((void**)&ff,    g_ff);
    cudaGetSymbolAddress((void**)&xh,    g_xh);
    cudaGetSymbolAddress((void**)&hpp,   g_hpp);
    cudaGetSymbolAddress((void**)&mp,    g_mpack);
    cudaGetSymbolAddress((void**)&weT,   g_weT);
    cudaGetSymbolAddress((void**)&wqkvT, g_wqkvT);
    cudaGetSymbolAddress((void**)&woutT, g_woutT);
    cudaGetSymbolAddress((void**)&wff1T, g_wff1T);
    cudaGetSymbolAddress((void**)&wff2T, g_wff2T);

    // smem: 3 stages * (64+64) rows * PB bytes
    const int SM32 = 3 * (64*80 + 64*80);   // 30720
    const int SM16 = 3 * (64*48 + 64*48);   // 18432
    cudaFuncSetAttribute(gemm_hc<32>, cudaFuncAttributeMaxDynamicSharedMemorySize, SM32);
    cudaFuncSetAttribute(gemm_hc<16>, cudaFuncAttributeMaxDynamicSharedMemorySize, SM16);
    cudaFuncSetAttribute(attn_mma, cudaFuncAttributeMaxDynamicSharedMemorySize, ATTN_SMEM);

    prep_all<<<(N_PREP + 255)/256, 256>>>(x, We, Wq, Wk, Wv, Wout, Wff1, Wff2,
                                          xh, weT, wqkvT, woutT, wff1T, wff2T);
    maskpack_kernel<<<(BB*NN*(NN/32) + 255)/256, 256>>>(mask, mp);

    // embed: h = relu(x @ We), exact + fp16 copy
    gemm_hc<16><<<dim3(DD/64, ROWS/64), 128, SM16>>>(
        xh, weT, nullptr, nullptr, h, hh, ROWS, FIN, DD, 1, 0);

    for (int l = 0; l < LYR; l++){
        // fused QKV (fp16 out; Q section pre-scaled by SCL)
        gemm_hc<32><<<dim3(QKVN/64, ROWS/64), 128, SM32>>>(
            hh, wqkvT + (size_t)l * QKVN * DD, nullptr, nullptr,
            nullptr, qkv, ROWS, DD, QKVN, 0, 1);

        attn_mma<<<BB * HH, 256, ATTN_SMEM>>>(qkv, mp, heads);

        // h = h + heads @ Wout[l]  (exact + fp16)
        gemm_hc<32><<<dim3(DD/64, ROWS/64), 128, SM32>>>(
            heads, woutT + (size_t)l * DD * DD, nullptr, h,
            h, hh, ROWS, DD, DD, 0, 0);

        // ff = relu(h @ Wff1 + bff1)  (fp16 out only)
        gemm_hc<32><<<dim3(FF/64, ROWS/64), 128, SM32>>>(
            hh, wff1T + (size_t)l * FF * DD, bff1 + (size_t)l * FF, nullptr,
            nullptr, ff, ROWS, DD, FF, 1, 0);

        // h = h + ff @ Wff2 + bff2  (exact + fp16)
        gemm_hc<32><<<dim3(DD/64, ROWS/64), 128, SM32>>>(
            ff, wff2T + (size_t)l * FF * DD, bff2 + (size_t)l * DD, h,
            h, hh, ROWS, FF, DD, 0, 0);
    }

    pool_kernel<<<BB, DD>>>(h, Wp, hpp);
    readout_kernel<<<ROWS/128, 128>>>(h, hpp, Wr, br, out);
}

// round 14
// speedup vs baseline: 1.0777x; 1.0777x over previous
#include <cuda_runtime.h>
#include <cuda_fp16.h>
#include <math.h>
#include <stdint.h>

// Problem dims
#define LYR 3
#define HH  8
#define DD  128
#define DKK 16
#define FF  512
#define BB  32
#define NN  512
#define FIN 16
#define OUTD 3
#define ROWS (BB*NN)          // 16384
#define QKVN (3*DD)           // 384
#define SCL (0.25f * 1.44269504089f)
#define MASKVAL (-2e30f)
#define MINIT   (-1e30f)

// prep segment sizes
#define N_XH   (ROWS*FIN)
#define N_WE   (FIN*DD)
#define N_QKV  (LYR*QKVN*DD)
#define N_WOUT (LYR*DD*DD)
#define N_FF1  (LYR*FF*DD)
#define N_FF2  (LYR*DD*FF)
#define N_MASK (BB*NN*(NN/32))
#define N_PREP (N_XH+N_WE+N_QKV+N_WOUT+N_FF1+N_FF2+N_MASK)

// ---------------- scratch (__device__ globals; no allocation) ----------------
__device__ __align__(16) float  g_h[ROWS*DD];       // exact fp32 trunk
__device__ __align__(16) __half g_hh[ROWS*DD];      // fp16 trunk copy
__device__ __align__(16) __half g_qkv[ROWS*QKVN];   // Q section pre-scaled by SCL
__device__ __align__(16) __half g_heads[ROWS*DD];
__device__ __align__(16) __half g_ff[ROWS*FF];
__device__ __align__(16) __half g_xh[ROWS*FIN];
__device__ __align__(16) float  g_hpp[BB*DD];
__device__ __align__(16) unsigned g_mpack[N_MASK];
// transposed fp16 weights [N][K]
__device__ __align__(16) __half g_weT[DD*FIN];
__device__ __align__(16) __half g_wqkvT[LYR*QKVN*DD];
__device__ __align__(16) __half g_woutT[LYR*DD*DD];
__device__ __align__(16) __half g_wff1T[LYR*FF*DD];
__device__ __align__(16) __half g_wff2T[LYR*DD*FF];

// ---------------- helpers ----------------------------------------------------
__device__ __forceinline__ uint32_t smem_u32(const void* p){
    uint32_t a;
    asm("{ .reg .u64 t; cvta.to.shared.u64 t, %1; cvt.u32.u64 %0, t; }" : "=r"(a) : "l"(p));
    return a;
}
__device__ __forceinline__ void cpa16(uint32_t s, const void* g){
    asm volatile("cp.async.cg.shared.global [%0], [%1], 16;" :: "r"(s), "l"(g) : "memory");
}
__device__ __forceinline__ void ldsm4(uint32_t& r0, uint32_t& r1, uint32_t& r2, uint32_t& r3,
                                      uint32_t addr){
    asm volatile("ldmatrix.sync.aligned.m8n8.x4.shared.b16 {%0,%1,%2,%3}, [%4];"
                 : "=r"(r0), "=r"(r1), "=r"(r2), "=r"(r3) : "r"(addr));
}
__device__ __forceinline__ void ldsm4t(uint32_t& r0, uint32_t& r1, uint32_t& r2, uint32_t& r3,
                                       uint32_t addr){
    asm volatile("ldmatrix.sync.aligned.m8n8.x4.trans.shared.b16 {%0,%1,%2,%3}, [%4];"
                 : "=r"(r0), "=r"(r1), "=r"(r2), "=r"(r3) : "r"(addr));
}
__device__ __forceinline__ void mma_f16(float c[4], const uint32_t a[4],
                                        uint32_t b0, uint32_t b1){
    asm volatile("mma.sync.aligned.m16n8k16.row.col.f32.f16.f16.f32 "
        "{%0,%1,%2,%3},{%4,%5,%6,%7},{%8,%9},{%0,%1,%2,%3};\n"
        : "+f"(c[0]),"+f"(c[1]),"+f"(c[2]),"+f"(c[3])
        : "r"(a[0]),"r"(a[1]),"r"(a[2]),"r"(a[3]),"r"(b0),"r"(b1));
}
__device__ __forceinline__ uint32_t f16x2(float hi, float lo){
    uint32_t r; asm("cvt.rn.f16x2.f32 %0, %1, %2;" : "=r"(r) : "f"(hi), "f"(lo));
    return r;
}

// ---------------- fused prep (converts + transposes + mask pack) --------------
__global__ void prep_all(const float* __restrict__ x,   const float* __restrict__ We,
                         const float* __restrict__ Wq,  const float* __restrict__ Wk,
                         const float* __restrict__ Wv,  const float* __restrict__ Wout,
                         const float* __restrict__ Wff1,const float* __restrict__ Wff2,
                         const int* __restrict__ mask,
                         __half* __restrict__ xh,   __half* __restrict__ weT,
                         __half* __restrict__ wqkvT,__half* __restrict__ woutT,
                         __half* __restrict__ wff1T,__half* __restrict__ wff2T,
                         unsigned* __restrict__ mpack)
{
    int idx = blockIdx.x * 256 + threadIdx.x;
    if (idx < N_XH){ xh[idx] = __float2half_rn(x[idx]); return; }
    idx -= N_XH;
    if (idx < N_WE){
        int cc = idx / FIN, rr = idx % FIN;
        weT[idx] = __float2half_rn(We[rr * DD + cc]); return;
    }
    idx -= N_WE;
    if (idx < N_QKV){
        int l = idx / (QKVN*DD), rem = idx % (QKVN*DD);
        int n = rem / DD, d = rem % DD;
        int sel = n >> 7, hc = n & 127, h2 = hc >> 4, kk = hc & 15;
        const float* W = (sel == 0) ? Wq : (sel == 1) ? Wk : Wv;
        wqkvT[idx] = __float2half_rn(W[(((l*HH + h2)*DD) + d)*DKK + kk]); return;
    }
    idx -= N_QKV;
    if (idx < N_WOUT){
        int l = idx / (DD*DD), rem = idx % (DD*DD);
        int cc = rem / DD, rr = rem % DD;
        woutT[idx] = __float2half_rn(Wout[(size_t)l*DD*DD + rr*DD + cc]); return;
    }
    idx -= N_WOUT;
    if (idx < N_FF1){
        int l = idx / (FF*DD), rem = idx % (FF*DD);
        int cc = rem / DD, rr = rem % DD;
        wff1T[idx] = __float2half_rn(Wff1[(size_t)l*DD*FF + rr*FF + cc]); return;
    }
    idx -= N_FF1;
    if (idx < N_FF2){
        int l = idx / (DD*FF), rem = idx % (DD*FF);
        int cc = rem / FF, rr = rem % FF;
        wff2T[idx] = __float2half_rn(Wff2[(size_t)l*FF*DD + rr*DD + cc]); return;
    }
    idx -= N_FF2;
    if (idx < N_MASK){
        const int* src = mask + (size_t)idx * 32;
        unsigned v = 0;
#pragma unroll
        for (int j = 0; j < 32; j += 4){
            int4 mm = *(const int4*)(src + j);
            v |= ((unsigned)(mm.x != 0)) << (j    );
            v |= ((unsigned)(mm.y != 0)) << (j + 1);
            v |= ((unsigned)(mm.z != 0)) << (j + 2);
            v |= ((unsigned)(mm.w != 0)) << (j + 3);
        }
        mpack[idx] = v;
    }
}

// ---------------- full-K GEMM: barrier-free mainloop --------------------------
// A [M,K] rowmajor fp16, Bt [N,K] rowmajor fp16, K = NCHUNK*128.
// BM=128, BN=64, 256 thr = 8 warps (4m x 2n), warp tile 32x32 (proven mapping).
// NCHUNK==1: single smem stage, ONE barrier total, 32 LDSM + 64 HMMA unbroken.
// NCHUNK>1: 2-stage double buffer over 128-wide K chunks.
#define FK_PB     272                    // padded row bytes (128 halves + 16B)
#define FK_ABYTES (128*FK_PB)            // 34816
#define FK_STAGE  (FK_ABYTES + 64*FK_PB) // 52224

__device__ __forceinline__ void fk_load(uint32_t sbase, const __half* __restrict__ A,
                                        const __half* __restrict__ Bt, int K, int chunk,
                                        int brow, int bcol, int tid){
    const __half* a = A + (size_t)brow * K + chunk * 128;
#pragma unroll
    for (int j = 0; j < 8; j++){
        int id = tid + j * 256;
        int r = id >> 4, cc = id & 15;
        cpa16(sbase + r * FK_PB + cc * 16, a + (size_t)r * K + cc * 8);
    }
    const __half* b = Bt + (size_t)bcol * K + chunk * 128;
#pragma unroll
    for (int j = 0; j < 4; j++){
        int id = tid + j * 256;
        int r = id >> 4, cc = id & 15;
        cpa16(sbase + FK_ABYTES + r * FK_PB + cc * 16, b + (size_t)r * K + cc * 8);
    }
    asm volatile("cp.async.commit_group;" ::: "memory");
}

template<int NCHUNK>
__global__ __launch_bounds__(256)
void gemm_fk(const __half* __restrict__ A, const __half* __restrict__ Bt,
             const float* __restrict__ bias, const float* __restrict__ res,
             float* __restrict__ C, __half* __restrict__ Ch,
             int N, int do_relu, int scaleq)
{
    extern __shared__ char smraw[];
    const uint32_t smbase = smem_u32(smraw);

    const int tid = threadIdx.x, lane = tid & 31, wid = tid >> 5;
    const int wm = wid >> 1, wn = wid & 1;
    const int brow = blockIdx.y * 128, bcol = blockIdx.x * 64;
    const int K = NCHUNK * 128;

    float c[2][4][4];
#pragma unroll
    for (int mt = 0; mt < 2; mt++)
#pragma unroll
        for (int nt = 0; nt < 4; nt++)
#pragma unroll
            for (int i = 0; i < 4; i++) c[mt][nt][i] = 0.f;

    fk_load(smbase, A, Bt, K, 0, brow, bcol, tid);

    const int arow0 = wm * 32 + (lane & 15);
    const int ahi = lane >> 4;
    const int bhi = (lane >> 3) & 1;
    const int brfrag = wn * 32 + (lane & 7) + ((lane >> 4) << 3);

#pragma unroll
    for (int ck = 0; ck < NCHUNK; ck++){
        if (ck > 0) __syncthreads();                 // stage (ck+1)%2 free to refill
        if (ck + 1 < NCHUNK)
            fk_load(smbase + ((ck + 1) & 1) * FK_STAGE, A, Bt, K, ck + 1, brow, bcol, tid);
        if (ck + 1 < NCHUNK)
            asm volatile("cp.async.wait_group 1;" ::: "memory");
        else
            asm volatile("cp.async.wait_group 0;" ::: "memory");
        __syncthreads();

        const uint32_t sb = smbase + (ck & 1) * FK_STAGE;
#pragma unroll
        for (int ks = 0; ks < 8; ks++){
            uint32_t af[2][4];
#pragma unroll
            for (int mt = 0; mt < 2; mt++){
                int r = arow0 + mt * 16;
                ldsm4(af[mt][0], af[mt][1], af[mt][2], af[mt][3],
                      sb + r * FK_PB + (ks * 2 + ahi) * 16);
            }
            uint32_t bf[2][4];
#pragma unroll
            for (int pr = 0; pr < 2; pr++){
                int r = brfrag + pr * 16;
                ldsm4(bf[pr][0], bf[pr][1], bf[pr][2], bf[pr][3],
                      sb + FK_ABYTES + r * FK_PB + (ks * 2 + bhi) * 16);
            }
#pragma unroll
            for (int mt = 0; mt < 2; mt++)
#pragma unroll
                for (int pr = 0; pr < 2; pr++){
                    mma_f16(c[mt][2*pr],     af[mt], bf[pr][0], bf[pr][1]);
                    mma_f16(c[mt][2*pr + 1], af[mt], bf[pr][2], bf[pr][3]);
                }
        }
    }

    // ---- epilogue (registers only; no sync needed) ----
#pragma unroll
    for (int mt = 0; mt < 2; mt++){
        int r0 = brow + wm * 32 + mt * 16 + (lane >> 2);
#pragma unroll
        for (int nt = 0; nt < 4; nt++){
            int col = bcol + wn * 32 + nt * 8 + (lane & 3) * 2;
            float2 bb = make_float2(0.f, 0.f);
            if (bias) bb = *(const float2*)(bias + col);
            size_t off0 = (size_t)r0 * N + col;
            size_t off1 = (size_t)(r0 + 8) * N + col;
            float2 v0 = make_float2(c[mt][nt][0] + bb.x, c[mt][nt][1] + bb.y);
            float2 v1 = make_float2(c[mt][nt][2] + bb.x, c[mt][nt][3] + bb.y);
            if (res){
                float2 r0v = *(const float2*)(res + off0);
                float2 r1v = *(const float2*)(res + off1);
                v0.x += r0v.x; v0.y += r0v.y; v1.x += r1v.x; v1.y += r1v.y;
            }
            if (do_relu){
                v0.x = fmaxf(v0.x, 0.f); v0.y = fmaxf(v0.y, 0.f);
                v1.x = fmaxf(v1.x, 0.f); v1.y = fmaxf(v1.y, 0.f);
            }
            if (scaleq && col < DD){
                v0.x *= SCL; v0.y *= SCL; v1.x *= SCL; v1.y *= SCL;
            }
            if (C){
                *(float2*)(C + off0) = v0;
                *(float2*)(C + off1) = v1;
            }
            if (Ch){
                *(__half2*)(Ch + off0) = __floats2half2_rn(v0.x, v0.y);
                *(__half2*)(Ch + off1) = __floats2half2_rn(v1.x, v1.y);
            }
        }
    }
}

// ---------------- streaming mma.sync GEMM (embed, K=16) ----------------------
template<int BK>
__global__ __launch_bounds__(128)
void gemm_hc(const __half* __restrict__ A, const __half* __restrict__ Bt,
             const float* __restrict__ bias, const float* __restrict__ res,
             float* __restrict__ C, __half* __restrict__ Ch,
             int M, int K, int N, int do_relu, int scaleq)
{
    constexpr int BM = 64, BN = 64, S = 3, THR = 128;
    constexpr int CH = BK / 8;
    constexpr int PB = BK * 2 + 16;
    constexpr int ABYTES = BM * PB, BBYTES = BN * PB;
    constexpr int STAGE = ABYTES + BBYTES;
    constexpr int ACH = BM * CH, BCH = BN * CH;
    constexpr int KS = BK / 16;

    extern __shared__ char smraw[];
    const uint32_t smbase = smem_u32(smraw);

    const int tid = threadIdx.x, lane = tid & 31, wid = tid >> 5;
    const int wm = wid >> 1, wn = wid & 1;
    const int brow = blockIdx.y * BM, bcol = blockIdx.x * BN;
    const int ntile = K / BK;

    float c[2][4][4];
#pragma unroll
    for (int mt = 0; mt < 2; mt++)
#pragma unroll
        for (int nt = 0; nt < 4; nt++)
#pragma unroll
            for (int i = 0; i < 4; i++) c[mt][nt][i] = 0.f;

#pragma unroll
    for (int s = 0; s < S - 1; s++){
        if (s < ntile){
            uint32_t sb = smbase + s * STAGE;
#pragma unroll
            for (int j = 0; j < (ACH + THR - 1)/THR; j++){
                int id = tid + j * THR;
                if ((ACH % THR) == 0 || id < ACH){
                    int r = id / CH, cc = id % CH;
                    cpa16(sb + r * PB + cc * 16,
                          A + (size_t)(brow + r) * K + s * BK + cc * 8);
                }
            }
#pragma unroll
            for (int j = 0; j < (BCH + THR - 1)/THR; j++){
                int id = tid + j * THR;
                if ((BCH % THR) == 0 || id < BCH){
                    int r = id / CH, cc = id % CH;
                    cpa16(sb + ABYTES + r * PB + cc * 16,
                          Bt + (size_t)(bcol + r) * K + s * BK + cc * 8);
                }
            }
        }
        asm volatile("cp.async.commit_group;" ::: "memory");
    }

    const int arow0 = wm * 32 + (lane & 15);
    const int ahi = lane >> 4;
    const int bhi = (lane >> 3) & 1;
    const int brfrag = wn * 32 + (lane & 7) + ((lane >> 4) << 3);

    for (int t = 0; t < ntile; t++){
        asm volatile("cp.async.wait_group %0;" :: "n"(S - 2) : "memory");
        __syncthreads();

        {
            int tn = t + S - 1;
            if (tn < ntile){
                uint32_t sb = smbase + (tn % S) * STAGE;
#pragma unroll
                for (int j = 0; j < (ACH + THR - 1)/THR; j++){
                    int id = tid + j * THR;
                    if ((ACH % THR) == 0 || id < ACH){
                        int r = id / CH, cc = id % CH;
                        cpa16(sb + r * PB + cc * 16,
                              A + (size_t)(brow + r) * K + tn * BK + cc * 8);
                    }
                }
#pragma unroll
                for (int j = 0; j < (BCH + THR - 1)/THR; j++){
                    int id = tid + j * THR;
                    if ((BCH % THR) == 0 || id < BCH){
                        int r = id / CH, cc = id % CH;
                        cpa16(sb + ABYTES + r * PB + cc * 16,
                              Bt + (size_t)(bcol + r) * K + tn * BK + cc * 8);
                    }
                }
            }
            asm volatile("cp.async.commit_group;" ::: "memory");
        }

        uint32_t sb = smbase + (t % S) * STAGE;
#pragma unroll
        for (int ks = 0; ks < KS; ks++){
            uint32_t af[2][4];
#pragma unroll
            for (int mt = 0; mt < 2; mt++){
                int r = arow0 + mt * 16;
                ldsm4(af[mt][0], af[mt][1], af[mt][2], af[mt][3],
                      sb + r * PB + (ks * 2 + ahi) * 16);
            }
            uint32_t bf[2][4];
#pragma unroll
            for (int pr = 0; pr < 2; pr++){
                int r = brfrag + pr * 16;
                ldsm4(bf[pr][0], bf[pr][1], bf[pr][2], bf[pr][3],
                      sb + ABYTES + r * PB + (ks * 2 + bhi) * 16);
            }
#pragma unroll
            for (int mt = 0; mt < 2; mt++)
#pragma unroll
                for (int pr = 0; pr < 2; pr++){
                    mma_f16(c[mt][2*pr],     af[mt], bf[pr][0], bf[pr][1]);
                    mma_f16(c[mt][2*pr + 1], af[mt], bf[pr][2], bf[pr][3]);
                }
        }
    }

#pragma unroll
    for (int mt = 0; mt < 2; mt++){
        int r0 = brow + wm * 32 + mt * 16 + (lane >> 2);
#pragma unroll
        for (int nt = 0; nt < 4; nt++){
            int col = bcol + wn * 32 + nt * 8 + (lane & 3) * 2;
            float2 bb = make_float2(0.f, 0.f);
            if (bias) bb = *(const float2*)(bias + col);
            size_t off0 = (size_t)r0 * N + col;
            size_t off1 = (size_t)(r0 + 8) * N + col;
            float2 v0 = make_float2(c[mt][nt][0] + bb.x, c[mt][nt][1] + bb.y);
            float2 v1 = make_float2(c[mt][nt][2] + bb.x, c[mt][nt][3] + bb.y);
            if (res){
                float2 r0v = *(const float2*)(res + off0);
                float2 r1v = *(const float2*)(res + off1);
                v0.x += r0v.x; v0.y += r0v.y; v1.x += r1v.x; v1.y += r1v.y;
            }
            if (do_relu){
                v0.x = fmaxf(v0.x, 0.f); v0.y = fmaxf(v0.y, 0.f);
                v1.x = fmaxf(v1.x, 0.f); v1.y = fmaxf(v1.y, 0.f);
            }
            if (scaleq && col < DD){
                v0.x *= SCL; v0.y *= SCL; v1.x *= SCL; v1.y *= SCL;
            }
            if (C){
                *(float2*)(C + off0) = v0;
                *(float2*)(C + off1) = v1;
            }
            if (Ch){
                *(__half2*)(Ch + off0) = __floats2half2_rn(v0.x, v0.y);
                *(__half2*)(Ch + off1) = __floats2half2_rn(v1.x, v1.y);
            }
        }
    }
}

// ---------------- flash attention, all-fp16 MMA (Q pre-scaled) ---------------
#define KS_BYTES (NN*48)
#define ATTN_SMEM (2*KS_BYTES)

__global__ __launch_bounds__(256)
void attn_mma(const __half* __restrict__ qkv, const unsigned* __restrict__ mpack,
              __half* __restrict__ heads)
{
    extern __shared__ char smraw[];
    const uint32_t ksbase = smem_u32(smraw);
    const uint32_t vsbase = ksbase + KS_BYTES;

    const int b = blockIdx.x >> 3, h = blockIdx.x & 7;
    const int tid = threadIdx.x, lane = tid & 31, wid = tid >> 5;

    for (int i = tid; i < NN * 2; i += 256){
        int row = i >> 1, cc = i & 1;
        const __half* base = qkv + (size_t)(b * NN + row) * QKVN + h * DKK;
        *(uint4*)(smraw + row * 48 + cc * 16) = *(const uint4*)(base + DD + cc * 8);
        *(uint4*)(smraw + KS_BYTES + row * 48 + cc * 16) =
            *(const uint4*)(base + 2 * DD + cc * 8);
    }
    __syncthreads();

    const __half* Qb = qkv + (size_t)(b * NN) * QKVN + h * DKK;
    const int bfr = (lane & 7) + ((lane >> 4) << 3);
    const int bhi = (lane >> 3) & 1;
    const int vcol = (lane >> 4) << 4;

    for (int qb = 0; qb < 4; qb++){
        const int qrow = qb * 128 + wid * 16 + (lane >> 2);

        uint32_t aq[4];
        {
            const __half* q0 = Qb + (size_t)qrow * QKVN + (lane & 3) * 2;
            const __half* q1 = Qb + (size_t)(qrow + 8) * QKVN + (lane & 3) * 2;
            aq[0] = *(const uint32_t*)q0;
            aq[1] = *(const uint32_t*)q1;
            aq[2] = *(const uint32_t*)(q0 + 8);
            aq[3] = *(const uint32_t*)(q1 + 8);
        }

        float m0 = MINIT, m1 = MINIT, l0 = 0.f, l1 = 0.f;
        float o[2][4];
#pragma unroll
        for (int vt = 0; vt < 2; vt++)
#pragma unroll
            for (int i = 0; i < 4; i++) o[vt][i] = 0.f;

        for (int kb = 0; kb < 8; kb++){
            float s[8][4];
#pragma unroll
            for (int nt = 0; nt < 8; nt++)
                s[nt][0] = s[nt][1] = s[nt][2] = s[nt][3] = 0.f;
#pragma unroll
            for (int pr = 0; pr < 4; pr++){
                int rn = kb * 64 + pr * 16 + bfr;
                uint32_t b0, b1, b2, b3;
                ldsm4(b0, b1, b2, b3, ksbase + rn * 48 + bhi * 16);
                mma_f16(s[2*pr],     aq, b0, b1);
                mma_f16(s[2*pr + 1], aq, b2, b3);
            }
            const unsigned* mpr = mpack + ((size_t)(b * NN + qrow) << 4) + kb * 2;
            unsigned mw00 = mpr[0], mw01 = mpr[1];
            unsigned mw10 = mpr[8 * 16], mw11 = mpr[8 * 16 + 1];
#pragma unroll
            for (int nt = 0; nt < 8; nt++){
                int cb = nt * 8 + (lane & 3) * 2;
                unsigned wlo = (cb & 32) ? mw01 : mw00;
                unsigned whi = (cb & 32) ? mw11 : mw10;
                int bit = cb & 31;
                s[nt][0] = ((wlo >> bit)       & 1) ? s[nt][0] : MASKVAL;
                s[nt][1] = ((wlo >> (bit + 1)) & 1) ? s[nt][1] : MASKVAL;
                s[nt][2] = ((whi >> bit)       & 1) ? s[nt][2] : MASKVAL;
                s[nt][3] = ((whi >> (bit + 1)) & 1) ? s[nt][3] : MASKVAL;
            }
            float rx0 = MASKVAL, rx1 = MASKVAL;
#pragma unroll
            for (int nt = 0; nt < 8; nt++){
                rx0 = fmaxf(rx0, fmaxf(s[nt][0], s[nt][1]));
                rx1 = fmaxf(rx1, fmaxf(s[nt][2], s[nt][3]));
            }
            rx0 = fmaxf(rx0, __shfl_xor_sync(0xffffffffu, rx0, 1));
            rx0 = fmaxf(rx0, __shfl_xor_sync(0xffffffffu, rx0, 2));
            rx1 = fmaxf(rx1, __shfl_xor_sync(0xffffffffu, rx1, 1));
            rx1 = fmaxf(rx1, __shfl_xor_sync(0xffffffffu, rx1, 2));
            float nm0 = fmaxf(m0, rx0), nm1 = fmaxf(m1, rx1);
            float f0 = exp2f(m0 - nm0), f1 = exp2f(m1 - nm1);
            m0 = nm0; m1 = nm1;
            l0 *= f0;  l1 *= f1;
#pragma unroll
            for (int vt = 0; vt < 2; vt++){
                o[vt][0] *= f0; o[vt][1] *= f0;
                o[vt][2] *= f1; o[vt][3] *= f1;
            }
#pragma unroll
            for (int nt = 0; nt < 8; nt++){
                s[nt][0] = exp2f(s[nt][0] - m0);
                s[nt][1] = exp2f(s[nt][1] - m0);
                s[nt][2] = exp2f(s[nt][2] - m1);
                s[nt][3] = exp2f(s[nt][3] - m1);
                l0 += s[nt][0] + s[nt][1];
                l1 += s[nt][2] + s[nt][3];
            }
#pragma unroll
            for (int kt = 0; kt < 4; kt++){
                uint32_t pa[4];
                pa[0] = f16x2(s[2 * kt][1],     s[2 * kt][0]);
                pa[1] = f16x2(s[2 * kt][3],     s[2 * kt][2]);
                pa[2] = f16x2(s[2 * kt + 1][1], s[2 * kt + 1][0]);
                pa[3] = f16x2(s[2 * kt + 1][3], s[2 * kt + 1][2]);
                int rv = kb * 64 + kt * 16 + (lane & 15);
                uint32_t vb0, vb1, vb2, vb3;
                ldsm4t(vb0, vb1, vb2, vb3, vsbase + rv * 48 + vcol);
                mma_f16(o[0], pa, vb0, vb1);
                mma_f16(o[1], pa, vb2, vb3);
            }
        }

        l0 += __shfl_xor_sync(0xffffffffu, l0, 1);
        l0 += __shfl_xor_sync(0xffffffffu, l0, 2);
        l1 += __shfl_xor_sync(0xffffffffu, l1, 1);
        l1 += __shfl_xor_sync(0xffffffffu, l1, 2);
        float i0 = 1.f / l0, i1 = 1.f / l1;
#pragma unroll
        for (int vt = 0; vt < 2; vt++){
            int col = h * DKK + vt * 8 + (lane & 3) * 2;
            *(__half2*)&heads[(size_t)(b * NN + qrow) * DD + col] =
                __floats2half2_rn(o[vt][0] * i0, o[vt][1] * i0);
            *(__half2*)&heads[(size_t)(b * NN + qrow + 8) * DD + col] =
                __floats2half2_rn(o[vt][2] * i1, o[vt][3] * i1);
        }
    }
}

// ---------------- pooling + Wp ------------------------------------------------
__global__ void pool_kernel(const float* __restrict__ h, const float* __restrict__ Wp,
                            float* __restrict__ hpp)
{
    __shared__ float mean[DD];
    int b = blockIdx.x, d = threadIdx.x;
    const float* hp = h + (size_t)b * NN * DD + d;
    float s = 0.f;
    for (int n = 0; n < NN; n++) s += hp[(size_t)n * DD];
    mean[d] = s * (1.f / (float)NN);
    __syncthreads();
    float acc = 0.f;
#pragma unroll 4
    for (int i = 0; i < DD; i++) acc += mean[i] * Wp[i * DD + d];
    hpp[b * DD + d] = acc;
}

// ---------------- readout ----------------------------------------------------
__global__ void readout_kernel(const float* __restrict__ h, const float* __restrict__ hpp,
                               const float* __restrict__ Wr, const float* __restrict__ br,
                               float* __restrict__ out)
{
    __shared__ float WrS[2 * DD * OUTD];
    __shared__ float brS[OUTD];
    int tid = threadIdx.x;
    for (int i = tid; i < 2 * DD * OUTD; i += 128) WrS[i] = Wr[i];
    if (tid < OUTD) brS[tid] = br[tid];
    __syncthreads();

    int row = blockIdx.x * 128 + tid;
    int b = row >> 9;
    float a0 = brS[0], a1 = brS[1], a2 = brS[2];
    const float* hp = hpp + b * DD;
#pragma unroll 4
    for (int i = 0; i < DD; i++){
        float f = fmaxf(hp[i], 0.f);
        a0 += f * WrS[i * 3 + 0]; a1 += f * WrS[i * 3 + 1]; a2 += f * WrS[i * 3 + 2];
    }
    const float* hr = h + (size_t)row * DD;
#pragma unroll 4
    for (int i = 0; i < DD; i++){
        float f = fmaxf(hr[i], 0.f);
        a0 += f * WrS[(DD + i) * 3 + 0];
        a1 += f * WrS[(DD + i) * 3 + 1];
        a2 += f * WrS[(DD + i) * 3 + 2];
    }
    out[row * 3 + 0] = a0; out[row * 3 + 1] = a1; out[row * 3 + 2] = a2;
}

// ---------------- host launcher ----------------------------------------------
extern "C" void kernel_launch(void* const* d_in, const int* in_sizes, int n_in,
                              void* d_out, int out_size)
{
    const float* x    = (const float*)d_in[0];
    const int*   mask = (const int*)  d_in[1];
    const float* We   = (const float*)d_in[2];
    const float* Wq   = (const float*)d_in[3];
    const float* Wk   = (const float*)d_in[4];
    const float* Wv   = (const float*)d_in[5];
    const float* Wout = (const float*)d_in[6];
    const float* Wff1 = (const float*)d_in[7];
    const float* bff1 = (const float*)d_in[8];
    const float* Wff2 = (const float*)d_in[9];
    const float* bff2 = (const float*)d_in[10];
    const float* Wp   = (const float*)d_in[11];
    const float* Wr   = (const float*)d_in[12];
    const float* br   = (const float*)d_in[13];
    float* out = (float*)d_out;

    float *h, *hpp;
    __half *hh, *qkv, *heads, *ff, *xh, *weT, *wqkvT, *woutT, *wff1T, *wff2T;
    unsigned* mp;
    cudaGetSymbolAddress((void**)&h,     g_h);
    cudaGetSymbolAddress((void**)&hh,    g_hh);
    cudaGetSymbolAddress((void**)&qkv,   g_qkv);
    cudaGetSymbolAddress((void**)&heads, g_heads);
    cudaGetSymbolAddress((void**)&ff,    g_ff);
    cudaGetSymbolAddress((void**)&xh,    g_xh);
    cudaGetSymbolAddress((void**)&hpp,   g_hpp);
    cudaGetSymbolAddress((void**)&mp,    g_mpack);
    cudaGetSymbolAddress((void**)&weT,   g_weT);
    cudaGetSymbolAddress((void**)&wqkvT, g_wqkvT);
    cudaGetSymbolAddress((void**)&woutT, g_woutT);
    cudaGetSymbolAddress((void**)&wff1T, g_wff1T);
    cudaGetSymbolAddress((void**)&wff2T, g_wff2T);

    const int SM16 = 3 * (64*48 + 64*48);       // embed streaming kernel
    const int FK1  = FK_STAGE;                  // 52224
    const int FK4  = 2 * FK_STAGE;              // 104448
    cudaFuncSetAttribute(gemm_hc<16>, cudaFuncAttributeMaxDynamicSharedMemorySize, SM16);
    cudaFuncSetAttribute(gemm_fk<1>, cudaFuncAttributeMaxDynamicSharedMemorySize, FK1);
    cudaFuncSetAttribute(gemm_fk<4>, cudaFuncAttributeMaxDynamicSharedMemorySize, FK4);
    cudaFuncSetAttribute(attn_mma, cudaFuncAttributeMaxDynamicSharedMemorySize, ATTN_SMEM);

    prep_all<<<(N_PREP + 255)/256, 256>>>(x, We, Wq, Wk, Wv, Wout, Wff1, Wff2, mask,
                                          xh, weT, wqkvT, woutT, wff1T, wff2T, mp);

    // embed: h = relu(x @ We), exact + fp16 copy (K=16)
    gemm_hc<16><<<dim3(DD/64, ROWS/64), 128, SM16>>>(
        xh, weT, nullptr, nullptr, h, hh, ROWS, FIN, DD, 1, 0);

    for (int l = 0; l < LYR; l++){
        // fused QKV (fp16 out; Q cols pre-scaled by SCL) — barrier-free K=128
        gemm_fk<1><<<dim3(QKVN/64, ROWS/128), 256, FK1>>>(
            hh, wqkvT + (size_t)l * QKVN * DD, nullptr, nullptr,
            nullptr, qkv, QKVN, 0, 1);

        attn_mma<<<BB * HH, 256, ATTN_SMEM>>>(qkv, mp, heads);

        // h = h + heads @ Wout[l]  (exact + fp16) — barrier-free K=128
        gemm_fk<1><<<dim3(DD/64, ROWS/128), 256, FK1>>>(
            heads, woutT + (size_t)l * DD * DD, nullptr, h,
            h, hh, DD, 0, 0);

        // ff = relu(h @ Wff1 + bff1) — barrier-free K=128
        gemm_fk<1><<<dim3(FF/64, ROWS/128), 256, FK1>>>(
            hh, wff1T + (size_t)l * FF * DD, bff1 + (size_t)l * FF, nullptr,
            nullptr, ff, FF, 1, 0);

        // h = h + ff @ Wff2 + bff2 — K=512, 4 double-buffered chunks
        gemm_fk<4><<<dim3(DD/64, ROWS/128), 256, FK4>>>(
            ff, wff2T + (size_t)l * DD * FF, bff2 + (size_t)l * DD, h,
            h, hh, DD, 0, 0);
    }

    pool_kernel<<<BB, DD>>>(h, Wp, hpp);
    readout_kernel<<<ROWS/128, 128>>>(h, hpp, Wr, br, out);
}

// round 15
// speedup vs baseline: 1.0992x; 1.0199x over previous
#include <cuda_runtime.h>
#include <cuda_fp16.h>
#include <math.h>
#include <stdint.h>

// Problem dims
#define LYR 3
#define HH  8
#define DD  128
#define DKK 16
#define FF  512
#define BB  32
#define NN  512
#define FIN 16
#define OUTD 3
#define ROWS (BB*NN)          // 16384
#define QKVN (3*DD)           // 384
#define SCL (0.25f * 1.44269504089f)
#define MASKVAL (-2e30f)
#define MINIT   (-1e30f)

// prep segment sizes
#define N_XH   (ROWS*FIN)
#define N_WE   (FIN*DD)
#define N_QKV  (LYR*QKVN*DD)
#define N_WOUT (LYR*DD*DD)
#define N_FF1  (LYR*FF*DD)
#define N_FF2  (LYR*DD*FF)
#define N_MASK (BB*NN*(NN/32))
#define N_PREP (N_XH+N_WE+N_QKV+N_WOUT+N_FF1+N_FF2+N_MASK)

// ---------------- scratch (__device__ globals; no allocation) ----------------
__device__ __align__(16) float  g_h[ROWS*DD];       // exact fp32 trunk
__device__ __align__(16) __half g_hh[ROWS*DD];      // fp16 trunk copy
__device__ __align__(16) __half g_qkv[ROWS*QKVN];   // Q section pre-scaled by SCL
__device__ __align__(16) __half g_heads[ROWS*DD];
__device__ __align__(16) __half g_ff[ROWS*FF];
__device__ __align__(16) __half g_xh[ROWS*FIN];
__device__ __align__(16) float  g_hpp[BB*DD];
__device__ __align__(16) unsigned g_mpack[N_MASK];
// transposed fp16 weights [N][K]
__device__ __align__(16) __half g_weT[DD*FIN];
__device__ __align__(16) __half g_wqkvT[LYR*QKVN*DD];
__device__ __align__(16) __half g_woutT[LYR*DD*DD];
__device__ __align__(16) __half g_wff1T[LYR*FF*DD];
__device__ __align__(16) __half g_wff2T[LYR*DD*FF];

// ---------------- helpers ----------------------------------------------------
__device__ __forceinline__ uint32_t smem_u32(const void* p){
    uint32_t a;
    asm("{ .reg .u64 t; cvta.to.shared.u64 t, %1; cvt.u32.u64 %0, t; }" : "=r"(a) : "l"(p));
    return a;
}
__device__ __forceinline__ void cpa16(uint32_t s, const void* g){
    asm volatile("cp.async.cg.shared.global [%0], [%1], 16;" :: "r"(s), "l"(g) : "memory");
}
__device__ __forceinline__ void ldsm4(uint32_t& r0, uint32_t& r1, uint32_t& r2, uint32_t& r3,
                                      uint32_t addr){
    asm volatile("ldmatrix.sync.aligned.m8n8.x4.shared.b16 {%0,%1,%2,%3}, [%4];"
                 : "=r"(r0), "=r"(r1), "=r"(r2), "=r"(r3) : "r"(addr));
}
__device__ __forceinline__ void ldsm4t(uint32_t& r0, uint32_t& r1, uint32_t& r2, uint32_t& r3,
                                       uint32_t addr){
    asm volatile("ldmatrix.sync.aligned.m8n8.x4.trans.shared.b16 {%0,%1,%2,%3}, [%4];"
                 : "=r"(r0), "=r"(r1), "=r"(r2), "=r"(r3) : "r"(addr));
}
__device__ __forceinline__ void mma_f16(float c[4], const uint32_t a[4],
                                        uint32_t b0, uint32_t b1){
    asm volatile("mma.sync.aligned.m16n8k16.row.col.f32.f16.f16.f32 "
        "{%0,%1,%2,%3},{%4,%5,%6,%7},{%8,%9},{%0,%1,%2,%3};\n"
        : "+f"(c[0]),"+f"(c[1]),"+f"(c[2]),"+f"(c[3])
        : "r"(a[0]),"r"(a[1]),"r"(a[2]),"r"(a[3]),"r"(b0),"r"(b1));
}
__device__ __forceinline__ uint32_t f16x2(float hi, float lo){
    uint32_t r; asm("cvt.rn.f16x2.f32 %0, %1, %2;" : "=r"(r) : "f"(hi), "f"(lo));
    return r;
}

// ---------------- fused prep (converts + transposes + mask pack) --------------
__global__ void prep_all(const float* __restrict__ x,   const float* __restrict__ We,
                         const float* __restrict__ Wq,  const float* __restrict__ Wk,
                         const float* __restrict__ Wv,  const float* __restrict__ Wout,
                         const float* __restrict__ Wff1,const float* __restrict__ Wff2,
                         const int* __restrict__ mask,
                         __half* __restrict__ xh,   __half* __restrict__ weT,
                         __half* __restrict__ wqkvT,__half* __restrict__ woutT,
                         __half* __restrict__ wff1T,__half* __restrict__ wff2T,
                         unsigned* __restrict__ mpack)
{
    int idx = blockIdx.x * 256 + threadIdx.x;
    if (idx < N_XH){ xh[idx] = __float2half_rn(x[idx]); return; }
    idx -= N_XH;
    if (idx < N_WE){
        int cc = idx / FIN, rr = idx % FIN;
        weT[idx] = __float2half_rn(We[rr * DD + cc]); return;
    }
    idx -= N_WE;
    if (idx < N_QKV){
        int l = idx / (QKVN*DD), rem = idx % (QKVN*DD);
        int n = rem / DD, d = rem % DD;
        int sel = n >> 7, hc = n & 127, h2 = hc >> 4, kk = hc & 15;
        const float* W = (sel == 0) ? Wq : (sel == 1) ? Wk : Wv;
        wqkvT[idx] = __float2half_rn(W[(((l*HH + h2)*DD) + d)*DKK + kk]); return;
    }
    idx -= N_QKV;
    if (idx < N_WOUT){
        int l = idx / (DD*DD), rem = idx % (DD*DD);
        int cc = rem / DD, rr = rem % DD;
        woutT[idx] = __float2half_rn(Wout[(size_t)l*DD*DD + rr*DD + cc]); return;
    }
    idx -= N_WOUT;
    if (idx < N_FF1){
        int l = idx / (FF*DD), rem = idx % (FF*DD);
        int cc = rem / DD, rr = rem % DD;
        wff1T[idx] = __float2half_rn(Wff1[(size_t)l*DD*FF + rr*FF + cc]); return;
    }
    idx -= N_FF1;
    if (idx < N_FF2){
        int l = idx / (DD*FF), rem = idx % (DD*FF);
        int cc = rem / FF, rr = rem % FF;
        wff2T[idx] = __float2half_rn(Wff2[(size_t)l*FF*DD + rr*DD + cc]); return;
    }
    idx -= N_FF2;
    if (idx < N_MASK){
        const int* src = mask + (size_t)idx * 32;
        unsigned v = 0;
#pragma unroll
        for (int j = 0; j < 32; j += 4){
            int4 mm = *(const int4*)(src + j);
            v |= ((unsigned)(mm.x != 0)) << (j    );
            v |= ((unsigned)(mm.y != 0)) << (j + 1);
            v |= ((unsigned)(mm.z != 0)) << (j + 2);
            v |= ((unsigned)(mm.w != 0)) << (j + 3);
        }
        mpack[idx] = v;
    }
}

// ---------------- full-K GEMM: barrier-free mainloop (R14 winner) -------------
#define FK_PB     272
#define FK_ABYTES (128*FK_PB)
#define FK_STAGE  (FK_ABYTES + 64*FK_PB)

__device__ __forceinline__ void fk_load(uint32_t sbase, const __half* __restrict__ A,
                                        const __half* __restrict__ Bt, int K, int chunk,
                                        int brow, int bcol, int tid){
    const __half* a = A + (size_t)brow * K + chunk * 128;
#pragma unroll
    for (int j = 0; j < 8; j++){
        int id = tid + j * 256;
        int r = id >> 4, cc = id & 15;
        cpa16(sbase + r * FK_PB + cc * 16, a + (size_t)r * K + cc * 8);
    }
    const __half* b = Bt + (size_t)bcol * K + chunk * 128;
#pragma unroll
    for (int j = 0; j < 4; j++){
        int id = tid + j * 256;
        int r = id >> 4, cc = id & 15;
        cpa16(sbase + FK_ABYTES + r * FK_PB + cc * 16, b + (size_t)r * K + cc * 8);
    }
    asm volatile("cp.async.commit_group;" ::: "memory");
}

template<int NCHUNK>
__global__ __launch_bounds__(256)
void gemm_fk(const __half* __restrict__ A, const __half* __restrict__ Bt,
             const float* __restrict__ bias, const float* __restrict__ res,
             float* __restrict__ C, __half* __restrict__ Ch,
             int N, int do_relu, int scaleq)
{
    extern __shared__ char smraw[];
    const uint32_t smbase = smem_u32(smraw);

    const int tid = threadIdx.x, lane = tid & 31, wid = tid >> 5;
    const int wm = wid >> 1, wn = wid & 1;
    const int brow = blockIdx.y * 128, bcol = blockIdx.x * 64;
    const int K = NCHUNK * 128;

    float c[2][4][4];
#pragma unroll
    for (int mt = 0; mt < 2; mt++)
#pragma unroll
        for (int nt = 0; nt < 4; nt++)
#pragma unroll
            for (int i = 0; i < 4; i++) c[mt][nt][i] = 0.f;

    fk_load(smbase, A, Bt, K, 0, brow, bcol, tid);

    const int arow0 = wm * 32 + (lane & 15);
    const int ahi = lane >> 4;
    const int bhi = (lane >> 3) & 1;
    const int brfrag = wn * 32 + (lane & 7) + ((lane >> 4) << 3);

#pragma unroll
    for (int ck = 0; ck < NCHUNK; ck++){
        if (ck > 0) __syncthreads();
        if (ck + 1 < NCHUNK)
            fk_load(smbase + ((ck + 1) & 1) * FK_STAGE, A, Bt, K, ck + 1, brow, bcol, tid);
        if (ck + 1 < NCHUNK)
            asm volatile("cp.async.wait_group 1;" ::: "memory");
        else
            asm volatile("cp.async.wait_group 0;" ::: "memory");
        __syncthreads();

        const uint32_t sb = smbase + (ck & 1) * FK_STAGE;
#pragma unroll
        for (int ks = 0; ks < 8; ks++){
            uint32_t af[2][4];
#pragma unroll
            for (int mt = 0; mt < 2; mt++){
                int r = arow0 + mt * 16;
                ldsm4(af[mt][0], af[mt][1], af[mt][2], af[mt][3],
                      sb + r * FK_PB + (ks * 2 + ahi) * 16);
            }
            uint32_t bf[2][4];
#pragma unroll
            for (int pr = 0; pr < 2; pr++){
                int r = brfrag + pr * 16;
                ldsm4(bf[pr][0], bf[pr][1], bf[pr][2], bf[pr][3],
                      sb + FK_ABYTES + r * FK_PB + (ks * 2 + bhi) * 16);
            }
#pragma unroll
            for (int mt = 0; mt < 2; mt++)
#pragma unroll
                for (int pr = 0; pr < 2; pr++){
                    mma_f16(c[mt][2*pr],     af[mt], bf[pr][0], bf[pr][1]);
                    mma_f16(c[mt][2*pr + 1], af[mt], bf[pr][2], bf[pr][3]);
                }
        }
    }

#pragma unroll
    for (int mt = 0; mt < 2; mt++){
        int r0 = brow + wm * 32 + mt * 16 + (lane >> 2);
#pragma unroll
        for (int nt = 0; nt < 4; nt++){
            int col = bcol + wn * 32 + nt * 8 + (lane & 3) * 2;
            float2 bb = make_float2(0.f, 0.f);
            if (bias) bb = *(const float2*)(bias + col);
            size_t off0 = (size_t)r0 * N + col;
            size_t off1 = (size_t)(r0 + 8) * N + col;
            float2 v0 = make_float2(c[mt][nt][0] + bb.x, c[mt][nt][1] + bb.y);
            float2 v1 = make_float2(c[mt][nt][2] + bb.x, c[mt][nt][3] + bb.y);
            if (res){
                float2 r0v = *(const float2*)(res + off0);
                float2 r1v = *(const float2*)(res + off1);
                v0.x += r0v.x; v0.y += r0v.y; v1.x += r1v.x; v1.y += r1v.y;
            }
            if (do_relu){
                v0.x = fmaxf(v0.x, 0.f); v0.y = fmaxf(v0.y, 0.f);
                v1.x = fmaxf(v1.x, 0.f); v1.y = fmaxf(v1.y, 0.f);
            }
            if (scaleq && col < DD){
                v0.x *= SCL; v0.y *= SCL; v1.x *= SCL; v1.y *= SCL;
            }
            if (C){
                *(float2*)(C + off0) = v0;
                *(float2*)(C + off1) = v1;
            }
            if (Ch){
                *(__half2*)(Ch + off0) = __floats2half2_rn(v0.x, v0.y);
                *(__half2*)(Ch + off1) = __floats2half2_rn(v1.x, v1.y);
            }
        }
    }
}

// ---------------- streaming mma.sync GEMM (embed, K=16) ----------------------
template<int BK>
__global__ __launch_bounds__(128)
void gemm_hc(const __half* __restrict__ A, const __half* __restrict__ Bt,
             const float* __restrict__ bias, const float* __restrict__ res,
             float* __restrict__ C, __half* __restrict__ Ch,
             int M, int K, int N, int do_relu, int scaleq)
{
    constexpr int BM = 64, BN = 64, S = 3, THR = 128;
    constexpr int CH = BK / 8;
    constexpr int PB = BK * 2 + 16;
    constexpr int ABYTES = BM * PB, BBYTES = BN * PB;
    constexpr int STAGE = ABYTES + BBYTES;
    constexpr int ACH = BM * CH, BCH = BN * CH;
    constexpr int KS = BK / 16;

    extern __shared__ char smraw[];
    const uint32_t smbase = smem_u32(smraw);

    const int tid = threadIdx.x, lane = tid & 31, wid = tid >> 5;
    const int wm = wid >> 1, wn = wid & 1;
    const int brow = blockIdx.y * BM, bcol = blockIdx.x * BN;
    const int ntile = K / BK;

    float c[2][4][4];
#pragma unroll
    for (int mt = 0; mt < 2; mt++)
#pragma unroll
        for (int nt = 0; nt < 4; nt++)
#pragma unroll
            for (int i = 0; i < 4; i++) c[mt][nt][i] = 0.f;

#pragma unroll
    for (int s = 0; s < S - 1; s++){
        if (s < ntile){
            uint32_t sb = smbase + s * STAGE;
#pragma unroll
            for (int j = 0; j < (ACH + THR - 1)/THR; j++){
                int id = tid + j * THR;
                if ((ACH % THR) == 0 || id < ACH){
                    int r = id / CH, cc = id % CH;
                    cpa16(sb + r * PB + cc * 16,
                          A + (size_t)(brow + r) * K + s * BK + cc * 8);
                }
            }
#pragma unroll
            for (int j = 0; j < (BCH + THR - 1)/THR; j++){
                int id = tid + j * THR;
                if ((BCH % THR) == 0 || id < BCH){
                    int r = id / CH, cc = id % CH;
                    cpa16(sb + ABYTES + r * PB + cc * 16,
                          Bt + (size_t)(bcol + r) * K + s * BK + cc * 8);
                }
            }
        }
        asm volatile("cp.async.commit_group;" ::: "memory");
    }

    const int arow0 = wm * 32 + (lane & 15);
    const int ahi = lane >> 4;
    const int bhi = (lane >> 3) & 1;
    const int brfrag = wn * 32 + (lane & 7) + ((lane >> 4) << 3);

    for (int t = 0; t < ntile; t++){
        asm volatile("cp.async.wait_group %0;" :: "n"(S - 2) : "memory");
        __syncthreads();

        {
            int tn = t + S - 1;
            if (tn < ntile){
                uint32_t sb = smbase + (tn % S) * STAGE;
#pragma unroll
                for (int j = 0; j < (ACH + THR - 1)/THR; j++){
                    int id = tid + j * THR;
                    if ((ACH % THR) == 0 || id < ACH){
                        int r = id / CH, cc = id % CH;
                        cpa16(sb + r * PB + cc * 16,
                              A + (size_t)(brow + r) * K + tn * BK + cc * 8);
                    }
                }
#pragma unroll
                for (int j = 0; j < (BCH + THR - 1)/THR; j++){
                    int id = tid + j * THR;
                    if ((BCH % THR) == 0 || id < BCH){
                        int r = id / CH, cc = id % CH;
                        cpa16(sb + ABYTES + r * PB + cc * 16,
                              Bt + (size_t)(bcol + r) * K + tn * BK + cc * 8);
                    }
                }
            }
            asm volatile("cp.async.commit_group;" ::: "memory");
        }

        uint32_t sb = smbase + (t % S) * STAGE;
#pragma unroll
        for (int ks = 0; ks < KS; ks++){
            uint32_t af[2][4];
#pragma unroll
            for (int mt = 0; mt < 2; mt++){
                int r = arow0 + mt * 16;
                ldsm4(af[mt][0], af[mt][1], af[mt][2], af[mt][3],
                      sb + r * PB + (ks * 2 + ahi) * 16);
            }
            uint32_t bf[2][4];
#pragma unroll
            for (int pr = 0; pr < 2; pr++){
                int r = brfrag + pr * 16;
                ldsm4(bf[pr][0], bf[pr][1], bf[pr][2], bf[pr][3],
                      sb + ABYTES + r * PB + (ks * 2 + bhi) * 16);
            }
#pragma unroll
            for (int mt = 0; mt < 2; mt++)
#pragma unroll
                for (int pr = 0; pr < 2; pr++){
                    mma_f16(c[mt][2*pr],     af[mt], bf[pr][0], bf[pr][1]);
                    mma_f16(c[mt][2*pr + 1], af[mt], bf[pr][2], bf[pr][3]);
                }
        }
    }

#pragma unroll
    for (int mt = 0; mt < 2; mt++){
        int r0 = brow + wm * 32 + mt * 16 + (lane >> 2);
#pragma unroll
        for (int nt = 0; nt < 4; nt++){
            int col = bcol + wn * 32 + nt * 8 + (lane & 3) * 2;
            float2 bb = make_float2(0.f, 0.f);
            if (bias) bb = *(const float2*)(bias + col);
            size_t off0 = (size_t)r0 * N + col;
            size_t off1 = (size_t)(r0 + 8) * N + col;
            float2 v0 = make_float2(c[mt][nt][0] + bb.x, c[mt][nt][1] + bb.y);
            float2 v1 = make_float2(c[mt][nt][2] + bb.x, c[mt][nt][3] + bb.y);
            if (res){
                float2 r0v = *(const float2*)(res + off0);
                float2 r1v = *(const float2*)(res + off1);
                v0.x += r0v.x; v0.y += r0v.y; v1.x += r1v.x; v1.y += r1v.y;
            }
            if (do_relu){
                v0.x = fmaxf(v0.x, 0.f); v0.y = fmaxf(v0.y, 0.f);
                v1.x = fmaxf(v1.x, 0.f); v1.y = fmaxf(v1.y, 0.f);
            }
            if (scaleq && col < DD){
                v0.x *= SCL; v0.y *= SCL; v1.x *= SCL; v1.y *= SCL;
            }
            if (C){
                *(float2*)(C + off0) = v0;
                *(float2*)(C + off1) = v1;
            }
            if (Ch){
                *(__half2*)(Ch + off0) = __floats2half2_rn(v0.x, v0.y);
                *(__half2*)(Ch + off1) = __floats2half2_rn(v1.x, v1.y);
            }
        }
    }
}

// ---------------- flash attention (qb-split x2, ones-mma denominator) --------
#define KS_BYTES (NN*48)
#define ATTN_SMEM (2*KS_BYTES)

__global__ __launch_bounds__(256)
void attn_mma(const __half* __restrict__ qkv, const unsigned* __restrict__ mpack,
              __half* __restrict__ heads)
{
    extern __shared__ char smraw[];
    const uint32_t ksbase = smem_u32(smraw);
    const uint32_t vsbase = ksbase + KS_BYTES;

    const int bid = blockIdx.x;
    const int b = bid >> 4, h = (bid >> 1) & 7, qh = bid & 1;
    const int tid = threadIdx.x, lane = tid & 31, wid = tid >> 5;

    for (int i = tid; i < NN * 2; i += 256){
        int row = i >> 1, cc = i & 1;
        const __half* base = qkv + (size_t)(b * NN + row) * QKVN + h * DKK;
        *(uint4*)(smraw + row * 48 + cc * 16) = *(const uint4*)(base + DD + cc * 8);
        *(uint4*)(smraw + KS_BYTES + row * 48 + cc * 16) =
            *(const uint4*)(base + 2 * DD + cc * 8);
    }
    __syncthreads();

    const __half* Qb = qkv + (size_t)(b * NN) * QKVN + h * DKK;
    const int bfr = (lane & 7) + ((lane >> 4) << 3);
    const int bhi = (lane >> 3) & 1;
    const int vcol = (lane >> 4) << 4;
    // ones B-tile for row-sum mma: column n=0 all ones (lanes 0-3), else 0
    const uint32_t bones = ((lane >> 2) == 0) ? 0x3C003C00u : 0u;

    for (int qi = 0; qi < 2; qi++){
        const int qb = qh * 2 + qi;
        const int qrow = qb * 128 + wid * 16 + (lane >> 2);

        uint32_t aq[4];
        {
            const __half* q0 = Qb + (size_t)qrow * QKVN + (lane & 3) * 2;
            const __half* q1 = Qb + (size_t)(qrow + 8) * QKVN + (lane & 3) * 2;
            aq[0] = *(const uint32_t*)q0;
            aq[1] = *(const uint32_t*)q1;
            aq[2] = *(const uint32_t*)(q0 + 8);
            aq[3] = *(const uint32_t*)(q1 + 8);
        }

        float m0 = MINIT, m1 = MINIT;
        float o[2][4], o2[4];
#pragma unroll
        for (int vt = 0; vt < 2; vt++)
#pragma unroll
            for (int i = 0; i < 4; i++) o[vt][i] = 0.f;
#pragma unroll
        for (int i = 0; i < 4; i++) o2[i] = 0.f;

        for (int kb = 0; kb < 8; kb++){
            float s[8][4];
#pragma unroll
            for (int nt = 0; nt < 8; nt++)
                s[nt][0] = s[nt][1] = s[nt][2] = s[nt][3] = 0.f;
#pragma unroll
            for (int pr = 0; pr < 4; pr++){
                int rn = kb * 64 + pr * 16 + bfr;
                uint32_t b0, b1, b2, b3;
                ldsm4(b0, b1, b2, b3, ksbase + rn * 48 + bhi * 16);
                mma_f16(s[2*pr],     aq, b0, b1);
                mma_f16(s[2*pr + 1], aq, b2, b3);
            }
            // mask (Q already carries SCL)
            const unsigned* mpr = mpack + ((size_t)(b * NN + qrow) << 4) + kb * 2;
            unsigned mw00 = mpr[0], mw01 = mpr[1];
            unsigned mw10 = mpr[8 * 16], mw11 = mpr[8 * 16 + 1];
#pragma unroll
            for (int nt = 0; nt < 8; nt++){
                int cb = nt * 8 + (lane & 3) * 2;
                unsigned wlo = (cb & 32) ? mw01 : mw00;
                unsigned whi = (cb & 32) ? mw11 : mw10;
                int bit = cb & 31;
                s[nt][0] = ((wlo >> bit)       & 1) ? s[nt][0] : MASKVAL;
                s[nt][1] = ((wlo >> (bit + 1)) & 1) ? s[nt][1] : MASKVAL;
                s[nt][2] = ((whi >> bit)       & 1) ? s[nt][2] : MASKVAL;
                s[nt][3] = ((whi >> (bit + 1)) & 1) ? s[nt][3] : MASKVAL;
            }
            // online softmax (log2 domain); l comes from ones-mma below
            float rx0 = MASKVAL, rx1 = MASKVAL;
#pragma unroll
            for (int nt = 0; nt < 8; nt++){
                rx0 = fmaxf(rx0, fmaxf(s[nt][0], s[nt][1]));
                rx1 = fmaxf(rx1, fmaxf(s[nt][2], s[nt][3]));
            }
            rx0 = fmaxf(rx0, __shfl_xor_sync(0xffffffffu, rx0, 1));
            rx0 = fmaxf(rx0, __shfl_xor_sync(0xffffffffu, rx0, 2));
            rx1 = fmaxf(rx1, __shfl_xor_sync(0xffffffffu, rx1, 1));
            rx1 = fmaxf(rx1, __shfl_xor_sync(0xffffffffu, rx1, 2));
            float nm0 = fmaxf(m0, rx0), nm1 = fmaxf(m1, rx1);
            float f0 = exp2f(m0 - nm0), f1 = exp2f(m1 - nm1);
            m0 = nm0; m1 = nm1;
#pragma unroll
            for (int vt = 0; vt < 2; vt++){
                o[vt][0] *= f0; o[vt][1] *= f0;
                o[vt][2] *= f1; o[vt][3] *= f1;
            }
            o2[0] *= f0; o2[2] *= f1;
#pragma unroll
            for (int nt = 0; nt < 8; nt++){
                s[nt][0] = exp2f(s[nt][0] - m0);
                s[nt][1] = exp2f(s[nt][1] - m0);
                s[nt][2] = exp2f(s[nt][2] - m1);
                s[nt][3] = exp2f(s[nt][3] - m1);
            }
            // P @ V  (+ ones-column row-sum mma for the denominator)
#pragma unroll
            for (int kt = 0; kt < 4; kt++){
                uint32_t pa[4];
                pa[0] = f16x2(s[2 * kt][1],     s[2 * kt][0]);
                pa[1] = f16x2(s[2 * kt][3],     s[2 * kt][2]);
                pa[2] = f16x2(s[2 * kt + 1][1], s[2 * kt + 1][0]);
                pa[3] = f16x2(s[2 * kt + 1][3], s[2 * kt + 1][2]);
                int rv = kb * 64 + kt * 16 + (lane & 15);
                uint32_t vb0, vb1, vb2, vb3;
                ldsm4t(vb0, vb1, vb2, vb3, vsbase + rv * 48 + vcol);
                mma_f16(o[0], pa, vb0, vb1);
                mma_f16(o[1], pa, vb2, vb3);
                mma_f16(o2, pa, bones, bones);
            }
        }

        // denominator: row sums live in col 0 of o2 (lane with lane%4==0)
        float l0 = __shfl_sync(0xffffffffu, o2[0], lane & ~3);
        float l1 = __shfl_sync(0xffffffffu, o2[2], lane & ~3);
        float i0 = 1.f / l0, i1 = 1.f / l1;
#pragma unroll
        for (int vt = 0; vt < 2; vt++){
            int col = h * DKK + vt * 8 + (lane & 3) * 2;
            *(__half2*)&heads[(size_t)(b * NN + qrow) * DD + col] =
                __floats2half2_rn(o[vt][0] * i0, o[vt][1] * i0);
            *(__half2*)&heads[(size_t)(b * NN + qrow + 8) * DD + col] =
                __floats2half2_rn(o[vt][2] * i1, o[vt][3] * i1);
        }
    }
}

// ---------------- pooling + Wp ------------------------------------------------
__global__ void pool_kernel(const float* __restrict__ h, const float* __restrict__ Wp,
                            float* __restrict__ hpp)
{
    __shared__ float mean[DD];
    int b = blockIdx.x, d = threadIdx.x;
    const float* hp = h + (size_t)b * NN * DD + d;
    float s = 0.f;
    for (int n = 0; n < NN; n++) s += hp[(size_t)n * DD];
    mean[d] = s * (1.f / (float)NN);
    __syncthreads();
    float acc = 0.f;
#pragma unroll 4
    for (int i = 0; i < DD; i++) acc += mean[i] * Wp[i * DD + d];
    hpp[b * DD + d] = acc;
}

// ---------------- readout ----------------------------------------------------
__global__ void readout_kernel(const float* __restrict__ h, const float* __restrict__ hpp,
                               const float* __restrict__ Wr, const float* __restrict__ br,
                               float* __restrict__ out)
{
    __shared__ float WrS[2 * DD * OUTD];
    __shared__ float brS[OUTD];
    int tid = threadIdx.x;
    for (int i = tid; i < 2 * DD * OUTD; i += 128) WrS[i] = Wr[i];
    if (tid < OUTD) brS[tid] = br[tid];
    __syncthreads();

    int row = blockIdx.x * 128 + tid;
    int b = row >> 9;
    float a0 = brS[0], a1 = brS[1], a2 = brS[2];
    const float* hp = hpp + b * DD;
#pragma unroll 4
    for (int i = 0; i < DD; i++){
        float f = fmaxf(hp[i], 0.f);
        a0 += f * WrS[i * 3 + 0]; a1 += f * WrS[i * 3 + 1]; a2 += f * WrS[i * 3 + 2];
    }
    const float* hr = h + (size_t)row * DD;
#pragma unroll 4
    for (int i = 0; i < DD; i++){
        float f = fmaxf(hr[i], 0.f);
        a0 += f * WrS[(DD + i) * 3 + 0];
        a1 += f * WrS[(DD + i) * 3 + 1];
        a2 += f * WrS[(DD + i) * 3 + 2];
    }
    out[row * 3 + 0] = a0; out[row * 3 + 1] = a1; out[row * 3 + 2] = a2;
}

// ---------------- host launcher ----------------------------------------------
extern "C" void kernel_launch(void* const* d_in, const int* in_sizes, int n_in,
                              void* d_out, int out_size)
{
    const float* x    = (const float*)d_in[0];
    const int*   mask = (const int*)  d_in[1];
    const float* We   = (const float*)d_in[2];
    const float* Wq   = (const float*)d_in[3];
    const float* Wk   = (const float*)d_in[4];
    const float* Wv   = (const float*)d_in[5];
    const float* Wout = (const float*)d_in[6];
    const float* Wff1 = (const float*)d_in[7];
    const float* bff1 = (const float*)d_in[8];
    const float* Wff2 = (const float*)d_in[9];
    const float* bff2 = (const float*)d_in[10];
    const float* Wp   = (const float*)d_in[11];
    const float* Wr   = (const float*)d_in[12];
    const float* br   = (const float*)d_in[13];
    float* out = (float*)d_out;

    float *h, *hpp;
    __half *hh, *qkv, *heads, *ff, *xh, *weT, *wqkvT, *woutT, *wff1T, *wff2T;
    unsigned* mp;
    cudaGetSymbolAddress((void**)&h,     g_h);
    cudaGetSymbolAddress((void**)&hh,    g_hh);
    cudaGetSymbolAddress((void**)&qkv,   g_qkv);
    cudaGetSymbolAddress((void**)&heads, g_heads);
    cudaGetSymbolAddress((void**)&ff,    g_ff);
    cudaGetSymbolAddress((void**)&xh,    g_xh);
    cudaGetSymbolAddress((void**)&hpp,   g_hpp);
    cudaGetSymbolAddress((void**)&mp,    g_mpack);
    cudaGetSymbolAddress((void**)&weT,   g_weT);
    cudaGetSymbolAddress((void**)&wqkvT, g_wqkvT);
    cudaGetSymbolAddress((void**)&woutT, g_woutT);
    cudaGetSymbolAddress((void**)&wff1T, g_wff1T);
    cudaGetSymbolAddress((void**)&wff2T, g_wff2T);

    const int SM16 = 3 * (64*48 + 64*48);
    const int FK1  = FK_STAGE;
    const int FK4  = 2 * FK_STAGE;
    cudaFuncSetAttribute(gemm_hc<16>, cudaFuncAttributeMaxDynamicSharedMemorySize, SM16);
    cudaFuncSetAttribute(gemm_fk<1>, cudaFuncAttributeMaxDynamicSharedMemorySize, FK1);
    cudaFuncSetAttribute(gemm_fk<4>, cudaFuncAttributeMaxDynamicSharedMemorySize, FK4);
    cudaFuncSetAttribute(attn_mma, cudaFuncAttributeMaxDynamicSharedMemorySize, ATTN_SMEM);

    prep_all<<<(N_PREP + 255)/256, 256>>>(x, We, Wq, Wk, Wv, Wout, Wff1, Wff2, mask,
                                          xh, weT, wqkvT, woutT, wff1T, wff2T, mp);

    // embed: h = relu(x @ We), exact + fp16 copy (K=16)
    gemm_hc<16><<<dim3(DD/64, ROWS/64), 128, SM16>>>(
        xh, weT, nullptr, nullptr, h, hh, ROWS, FIN, DD, 1, 0);

    for (int l = 0; l < LYR; l++){
        // fused QKV (fp16 out; Q cols pre-scaled by SCL) — barrier-free K=128
        gemm_fk<1><<<dim3(QKVN/64, ROWS/128), 256, FK1>>>(
            hh, wqkvT + (size_t)l * QKVN * DD, nullptr, nullptr,
            nullptr, qkv, QKVN, 0, 1);

        // attention: grid split over (b, h, half) for occupancy
        attn_mma<<<BB * HH * 2, 256, ATTN_SMEM>>>(qkv, mp, heads);

        // h = h + heads @ Wout[l]  (exact + fp16) — barrier-free K=128
        gemm_fk<1><<<dim3(DD/64, ROWS/128), 256, FK1>>>(
            heads, woutT + (size_t)l * DD * DD, nullptr, h,
            h, hh, DD, 0, 0);

        // ff = relu(h @ Wff1 + bff1) — barrier-free K=128
        gemm_fk<1><<<dim3(FF/64, ROWS/128), 256, FK1>>>(
            hh, wff1T + (size_t)l * FF * DD, bff1 + (size_t)l * FF, nullptr,
            nullptr, ff, FF, 1, 0);

        // h = h + ff @ Wff2 + bff2 — K=512, 4 double-buffered chunks
        gemm_fk<4><<<dim3(DD/64, ROWS/128), 256, FK4>>>(
            ff, wff2T + (size_t)l * DD * FF, bff2 + (size_t)l * DD, h,
            h, hh, DD, 0, 0);
    }

    pool_kernel<<<BB, DD>>>(h, Wp, hpp);
    readout_kernel<<<ROWS/128, 128>>>(h, hpp, Wr, br, out);
}

// round 17
// speedup vs baseline: 1.2014x; 1.0930x over previous
#include <cuda_runtime.h>
#include <cuda_fp16.h>
#include <math.h>
#include <stdint.h>

// Problem dims
#define LYR 3
#define HH  8
#define DD  128
#define DKK 16
#define FF  512
#define BB  32
#define NN  512
#define FIN 16
#define OUTD 3
#define ROWS (BB*NN)          // 16384
#define QKVN (3*DD)           // 384
#define SCL (0.25f * 1.44269504089f)
#define MASKVAL (-2e30f)
#define MINIT   (-1e30f)

// prep segment sizes
#define N_XH   (ROWS*FIN)
#define N_WE   (FIN*DD)
#define N_QKV  (LYR*QKVN*DD)
#define N_WOUT (LYR*DD*DD)
#define N_FF1  (LYR*FF*DD)
#define N_FF2  (LYR*DD*FF)
#define N_MASK (BB*NN*(NN/32))
#define N_PREP (N_XH+N_WE+N_QKV+N_WOUT+N_FF1+N_FF2+N_MASK)

// ---------------- scratch (__device__ globals; no allocation) ----------------
__device__ __align__(16) float  g_h[ROWS*DD];       // exact fp32 trunk
__device__ __align__(16) __half g_hh[ROWS*DD];      // fp16 trunk copy
__device__ __align__(16) __half g_qkv[ROWS*QKVN];   // Q section pre-scaled by SCL
__device__ __align__(16) __half g_heads[ROWS*DD];
__device__ __align__(16) __half g_ff[ROWS*FF];
__device__ __align__(16) __half g_xh[ROWS*FIN];
__device__ __align__(16) float  g_hpp[BB*DD];
__device__ __align__(16) unsigned g_mpack[N_MASK];
// transposed fp16 weights [N][K]
__device__ __align__(16) __half g_weT[DD*FIN];
__device__ __align__(16) __half g_wqkvT[LYR*QKVN*DD];
__device__ __align__(16) __half g_woutT[LYR*DD*DD];
__device__ __align__(16) __half g_wff1T[LYR*FF*DD];
__device__ __align__(16) __half g_wff2T[LYR*DD*FF];

// ---------------- helpers ----------------------------------------------------
__device__ __forceinline__ uint32_t smem_u32(const void* p){
    uint32_t a;
    asm("{ .reg .u64 t; cvta.to.shared.u64 t, %1; cvt.u32.u64 %0, t; }" : "=r"(a) : "l"(p));
    return a;
}
__device__ __forceinline__ void cpa16(uint32_t s, const void* g){
    asm volatile("cp.async.cg.shared.global [%0], [%1], 16;" :: "r"(s), "l"(g) : "memory");
}
__device__ __forceinline__ void ldsm4(uint32_t& r0, uint32_t& r1, uint32_t& r2, uint32_t& r3,
                                      uint32_t addr){
    asm volatile("ldmatrix.sync.aligned.m8n8.x4.shared.b16 {%0,%1,%2,%3}, [%4];"
                 : "=r"(r0), "=r"(r1), "=r"(r2), "=r"(r3) : "r"(addr));
}
__device__ __forceinline__ void ldsm4t(uint32_t& r0, uint32_t& r1, uint32_t& r2, uint32_t& r3,
                                       uint32_t addr){
    asm volatile("ldmatrix.sync.aligned.m8n8.x4.trans.shared.b16 {%0,%1,%2,%3}, [%4];"
                 : "=r"(r0), "=r"(r1), "=r"(r2), "=r"(r3) : "r"(addr));
}
__device__ __forceinline__ void mma_f16(float c[4], const uint32_t a[4],
                                        uint32_t b0, uint32_t b1){
    asm volatile("mma.sync.aligned.m16n8k16.row.col.f32.f16.f16.f32 "
        "{%0,%1,%2,%3},{%4,%5,%6,%7},{%8,%9},{%0,%1,%2,%3};\n"
        : "+f"(c[0]),"+f"(c[1]),"+f"(c[2]),"+f"(c[3])
        : "r"(a[0]),"r"(a[1]),"r"(a[2]),"r"(a[3]),"r"(b0),"r"(b1));
}
__device__ __forceinline__ uint32_t f16x2(float hi, float lo){
    uint32_t r; asm("cvt.rn.f16x2.f32 %0, %1, %2;" : "=r"(r) : "f"(hi), "f"(lo));
    return r;
}
// hardware EX2 regardless of fast-math flags
__device__ __forceinline__ uint32_t ex2h2(uint32_t x){
    uint32_t r; asm("ex2.approx.f16x2 %0, %1;" : "=r"(r) : "r"(x));
    return r;
}
__device__ __forceinline__ float ex2f(float x){
    float r; asm("ex2.approx.ftz.f32 %0, %1;" : "=f"(r) : "f"(x));
    return r;
}

// ---------------- fused prep (converts + transposes + mask pack) --------------
__global__ void prep_all(const float* __restrict__ x,   const float* __restrict__ We,
                         const float* __restrict__ Wq,  const float* __restrict__ Wk,
                         const float* __restrict__ Wv,  const float* __restrict__ Wout,
                         const float* __restrict__ Wff1,const float* __restrict__ Wff2,
                         const int* __restrict__ mask,
                         __half* __restrict__ xh,   __half* __restrict__ weT,
                         __half* __restrict__ wqkvT,__half* __restrict__ woutT,
                         __half* __restrict__ wff1T,__half* __restrict__ wff2T,
                         unsigned* __restrict__ mpack)
{
    int idx = blockIdx.x * 256 + threadIdx.x;
    if (idx < N_XH){ xh[idx] = __float2half_rn(x[idx]); return; }
    idx -= N_XH;
    if (idx < N_WE){
        int cc = idx / FIN, rr = idx % FIN;
        weT[idx] = __float2half_rn(We[rr * DD + cc]); return;
    }
    idx -= N_WE;
    if (idx < N_QKV){
        int l = idx / (QKVN*DD), rem = idx % (QKVN*DD);
        int n = rem / DD, d = rem % DD;
        int sel = n >> 7, hc = n & 127, h2 = hc >> 4, kk = hc & 15;
        const float* W = (sel == 0) ? Wq : (sel == 1) ? Wk : Wv;
        wqkvT[idx] = __float2half_rn(W[(((l*HH + h2)*DD) + d)*DKK + kk]); return;
    }
    idx -= N_QKV;
    if (idx < N_WOUT){
        int l = idx / (DD*DD), rem = idx % (DD*DD);
        int cc = rem / DD, rr = rem % DD;
        woutT[idx] = __float2half_rn(Wout[(size_t)l*DD*DD + rr*DD + cc]); return;
    }
    idx -= N_WOUT;
    if (idx < N_FF1){
        int l = idx / (FF*DD), rem = idx % (FF*DD);
        int cc = rem / DD, rr = rem % DD;
        wff1T[idx] = __float2half_rn(Wff1[(size_t)l*DD*FF + rr*FF + cc]); return;
    }
    idx -= N_FF1;
    if (idx < N_FF2){
        int l = idx / (DD*FF), rem = idx % (DD*FF);
        int cc = rem / FF, rr = rem % FF;
        wff2T[idx] = __float2half_rn(Wff2[(size_t)l*FF*DD + rr*DD + cc]); return;
    }
    idx -= N_FF2;
    if (idx < N_MASK){
        const int* src = mask + (size_t)idx * 32;
        unsigned v = 0;
#pragma unroll
        for (int j = 0; j < 32; j += 4){
            int4 mm = *(const int4*)(src + j);
            v |= ((unsigned)(mm.x != 0)) << (j    );
            v |= ((unsigned)(mm.y != 0)) << (j + 1);
            v |= ((unsigned)(mm.z != 0)) << (j + 2);
            v |= ((unsigned)(mm.w != 0)) << (j + 3);
        }
        mpack[idx] = v;
    }
}

// ---------------- full-K GEMM: barrier-free mainloop (R14 winner) -------------
#define FK_PB     272
#define FK_ABYTES (128*FK_PB)
#define FK_STAGE  (FK_ABYTES + 64*FK_PB)

__device__ __forceinline__ void fk_load(uint32_t sbase, const __half* __restrict__ A,
                                        const __half* __restrict__ Bt, int K, int chunk,
                                        int brow, int bcol, int tid){
    const __half* a = A + (size_t)brow * K + chunk * 128;
#pragma unroll
    for (int j = 0; j < 8; j++){
        int id = tid + j * 256;
        int r = id >> 4, cc = id & 15;
        cpa16(sbase + r * FK_PB + cc * 16, a + (size_t)r * K + cc * 8);
    }
    const __half* b = Bt + (size_t)bcol * K + chunk * 128;
#pragma unroll
    for (int j = 0; j < 4; j++){
        int id = tid + j * 256;
        int r = id >> 4, cc = id & 15;
        cpa16(sbase + FK_ABYTES + r * FK_PB + cc * 16, b + (size_t)r * K + cc * 8);
    }
    asm volatile("cp.async.commit_group;" ::: "memory");
}

template<int NCHUNK>
__global__ __launch_bounds__(256)
void gemm_fk(const __half* __restrict__ A, const __half* __restrict__ Bt,
             const float* __restrict__ bias, const float* __restrict__ res,
             float* __restrict__ C, __half* __restrict__ Ch,
             int N, int do_relu, int scaleq)
{
    extern __shared__ char smraw[];
    const uint32_t smbase = smem_u32(smraw);

    const int tid = threadIdx.x, lane = tid & 31, wid = tid >> 5;
    const int wm = wid >> 1, wn = wid & 1;
    const int brow = blockIdx.y * 128, bcol = blockIdx.x * 64;
    const int K = NCHUNK * 128;

    float c[2][4][4];
#pragma unroll
    for (int mt = 0; mt < 2; mt++)
#pragma unroll
        for (int nt = 0; nt < 4; nt++)
#pragma unroll
            for (int i = 0; i < 4; i++) c[mt][nt][i] = 0.f;

    fk_load(smbase, A, Bt, K, 0, brow, bcol, tid);

    const int arow0 = wm * 32 + (lane & 15);
    const int ahi = lane >> 4;
    const int bhi = (lane >> 3) & 1;
    const int brfrag = wn * 32 + (lane & 7) + ((lane >> 4) << 3);

#pragma unroll
    for (int ck = 0; ck < NCHUNK; ck++){
        if (ck > 0) __syncthreads();
        if (ck + 1 < NCHUNK)
            fk_load(smbase + ((ck + 1) & 1) * FK_STAGE, A, Bt, K, ck + 1, brow, bcol, tid);
        if (ck + 1 < NCHUNK)
            asm volatile("cp.async.wait_group 1;" ::: "memory");
        else
            asm volatile("cp.async.wait_group 0;" ::: "memory");
        __syncthreads();

        const uint32_t sb = smbase + (ck & 1) * FK_STAGE;
#pragma unroll
        for (int ks = 0; ks < 8; ks++){
            uint32_t af[2][4];
#pragma unroll
            for (int mt = 0; mt < 2; mt++){
                int r = arow0 + mt * 16;
                ldsm4(af[mt][0], af[mt][1], af[mt][2], af[mt][3],
                      sb + r * FK_PB + (ks * 2 + ahi) * 16);
            }
            uint32_t bf[2][4];
#pragma unroll
            for (int pr = 0; pr < 2; pr++){
                int r = brfrag + pr * 16;
                ldsm4(bf[pr][0], bf[pr][1], bf[pr][2], bf[pr][3],
                      sb + FK_ABYTES + r * FK_PB + (ks * 2 + bhi) * 16);
            }
#pragma unroll
            for (int mt = 0; mt < 2; mt++)
#pragma unroll
                for (int pr = 0; pr < 2; pr++){
                    mma_f16(c[mt][2*pr],     af[mt], bf[pr][0], bf[pr][1]);
                    mma_f16(c[mt][2*pr + 1], af[mt], bf[pr][2], bf[pr][3]);
                }
        }
    }

#pragma unroll
    for (int mt = 0; mt < 2; mt++){
        int r0 = brow + wm * 32 + mt * 16 + (lane >> 2);
#pragma unroll
        for (int nt = 0; nt < 4; nt++){
            int col = bcol + wn * 32 + nt * 8 + (lane & 3) * 2;
            float2 bb = make_float2(0.f, 0.f);
            if (bias) bb = *(const float2*)(bias + col);
            size_t off0 = (size_t)r0 * N + col;
            size_t off1 = (size_t)(r0 + 8) * N + col;
            float2 v0 = make_float2(c[mt][nt][0] + bb.x, c[mt][nt][1] + bb.y);
            float2 v1 = make_float2(c[mt][nt][2] + bb.x, c[mt][nt][3] + bb.y);
            if (res){
                float2 r0v = *(const float2*)(res + off0);
                float2 r1v = *(const float2*)(res + off1);
                v0.x += r0v.x; v0.y += r0v.y; v1.x += r1v.x; v1.y += r1v.y;
            }
            if (do_relu){
                v0.x = fmaxf(v0.x, 0.f); v0.y = fmaxf(v0.y, 0.f);
                v1.x = fmaxf(v1.x, 0.f); v1.y = fmaxf(v1.y, 0.f);
            }
            if (scaleq && col < DD){
                v0.x *= SCL; v0.y *= SCL; v1.x *= SCL; v1.y *= SCL;
            }
            if (C){
                *(float2*)(C + off0) = v0;
                *(float2*)(C + off1) = v1;
            }
            if (Ch){
                *(__half2*)(Ch + off0) = __floats2half2_rn(v0.x, v0.y);
                *(__half2*)(Ch + off1) = __floats2half2_rn(v1.x, v1.y);
            }
        }
    }
}

// ---------------- streaming mma.sync GEMM (embed, K=16) ----------------------
template<int BK>
__global__ __launch_bounds__(128)
void gemm_hc(const __half* __restrict__ A, const __half* __restrict__ Bt,
             const float* __restrict__ bias, const float* __restrict__ res,
             float* __restrict__ C, __half* __restrict__ Ch,
             int M, int K, int N, int do_relu, int scaleq)
{
    constexpr int BM = 64, BN = 64, S = 3, THR = 128;
    constexpr int CH = BK / 8;
    constexpr int PB = BK * 2 + 16;
    constexpr int ABYTES = BM * PB, BBYTES = BN * PB;
    constexpr int STAGE = ABYTES + BBYTES;
    constexpr int ACH = BM * CH, BCH = BN * CH;
    constexpr int KS = BK / 16;

    extern __shared__ char smraw[];
    const uint32_t smbase = smem_u32(smraw);

    const int tid = threadIdx.x, lane = tid & 31, wid = tid >> 5;
    const int wm = wid >> 1, wn = wid & 1;
    const int brow = blockIdx.y * BM, bcol = blockIdx.x * BN;
    const int ntile = K / BK;

    float c[2][4][4];
#pragma unroll
    for (int mt = 0; mt < 2; mt++)
#pragma unroll
        for (int nt = 0; nt < 4; nt++)
#pragma unroll
            for (int i = 0; i < 4; i++) c[mt][nt][i] = 0.f;

#pragma unroll
    for (int s = 0; s < S - 1; s++){
        if (s < ntile){
            uint32_t sb = smbase + s * STAGE;
#pragma unroll
            for (int j = 0; j < (ACH + THR - 1)/THR; j++){
                int id = tid + j * THR;
                if ((ACH % THR) == 0 || id < ACH){
                    int r = id / CH, cc = id % CH;
                    cpa16(sb + r * PB + cc * 16,
                          A + (size_t)(brow + r) * K + s * BK + cc * 8);
                }
            }
#pragma unroll
            for (int j = 0; j < (BCH + THR - 1)/THR; j++){
                int id = tid + j * THR;
                if ((BCH % THR) == 0 || id < BCH){
                    int r = id / CH, cc = id % CH;
                    cpa16(sb + ABYTES + r * PB + cc * 16,
                          Bt + (size_t)(bcol + r) * K + s * BK + cc * 8);
                }
            }
        }
        asm volatile("cp.async.commit_group;" ::: "memory");
    }

    const int arow0 = wm * 32 + (lane & 15);
    const int ahi = lane >> 4;
    const int bhi = (lane >> 3) & 1;
    const int brfrag = wn * 32 + (lane & 7) + ((lane >> 4) << 3);

    for (int t = 0; t < ntile; t++){
        asm volatile("cp.async.wait_group %0;" :: "n"(S - 2) : "memory");
        __syncthreads();

        {
            int tn = t + S - 1;
            if (tn < ntile){
                uint32_t sb = smbase + (tn % S) * STAGE;
#pragma unroll
                for (int j = 0; j < (ACH + THR - 1)/THR; j++){
                    int id = tid + j * THR;
                    if ((ACH % THR) == 0 || id < ACH){
                        int r = id / CH, cc = id % CH;
                        cpa16(sb + r * PB + cc * 16,
                              A + (size_t)(brow + r) * K + tn * BK + cc * 8);
                    }
                }
#pragma unroll
                for (int j = 0; j < (BCH + THR - 1)/THR; j++){
                    int id = tid + j * THR;
                    if ((BCH % THR) == 0 || id < BCH){
                        int r = id / CH, cc = id % CH;
                        cpa16(sb + ABYTES + r * PB + cc * 16,
                              Bt + (size_t)(bcol + r) * K + tn * BK + cc * 8);
                    }
                }
            }
            asm volatile("cp.async.commit_group;" ::: "memory");
        }

        uint32_t sb = smbase + (t % S) * STAGE;
#pragma unroll
        for (int ks = 0; ks < KS; ks++){
            uint32_t af[2][4];
#pragma unroll
            for (int mt = 0; mt < 2; mt++){
                int r = arow0 + mt * 16;
                ldsm4(af[mt][0], af[mt][1], af[mt][2], af[mt][3],
                      sb + r * PB + (ks * 2 + ahi) * 16);
            }
            uint32_t bf[2][4];
#pragma unroll
            for (int pr = 0; pr < 2; pr++){
                int r = brfrag + pr * 16;
                ldsm4(bf[pr][0], bf[pr][1], bf[pr][2], bf[pr][3],
                      sb + ABYTES + r * PB + (ks * 2 + bhi) * 16);
            }
#pragma unroll
            for (int mt = 0; mt < 2; mt++)
#pragma unroll
                for (int pr = 0; pr < 2; pr++){
                    mma_f16(c[mt][2*pr],     af[mt], bf[pr][0], bf[pr][1]);
                    mma_f16(c[mt][2*pr + 1], af[mt], bf[pr][2], bf[pr][3]);
                }
        }
    }

#pragma unroll
    for (int mt = 0; mt < 2; mt++){
        int r0 = brow + wm * 32 + mt * 16 + (lane >> 2);
#pragma unroll
        for (int nt = 0; nt < 4; nt++){
            int col = bcol + wn * 32 + nt * 8 + (lane & 3) * 2;
            float2 bb = make_float2(0.f, 0.f);
            if (bias) bb = *(const float2*)(bias + col);
            size_t off0 = (size_t)r0 * N + col;
            size_t off1 = (size_t)(r0 + 8) * N + col;
            float2 v0 = make_float2(c[mt][nt][0] + bb.x, c[mt][nt][1] + bb.y);
            float2 v1 = make_float2(c[mt][nt][2] + bb.x, c[mt][nt][3] + bb.y);
            if (res){
                float2 r0v = *(const float2*)(res + off0);
                float2 r1v = *(const float2*)(res + off1);
                v0.x += r0v.x; v0.y += r0v.y; v1.x += r1v.x; v1.y += r1v.y;
            }
            if (do_relu){
                v0.x = fmaxf(v0.x, 0.f); v0.y = fmaxf(v0.y, 0.f);
                v1.x = fmaxf(v1.x, 0.f); v1.y = fmaxf(v1.y, 0.f);
            }
            if (scaleq && col < DD){
                v0.x *= SCL; v0.y *= SCL; v1.x *= SCL; v1.y *= SCL;
            }
            if (C){
                *(float2*)(C + off0) = v0;
                *(float2*)(C + off1) = v1;
            }
            if (Ch){
                *(__half2*)(Ch + off0) = __floats2half2_rn(v0.x, v0.y);
                *(__half2*)(Ch + off1) = __floats2half2_rn(v1.x, v1.y);
            }
        }
    }
}

// ---------------- flash attention (qb-split x4, hw EX2 fp16, ones-mma) -------
#define KS_BYTES (NN*48)
#define ATTN_SMEM (2*KS_BYTES)

__global__ __launch_bounds__(256)
void attn_mma(const __half* __restrict__ qkv, const unsigned* __restrict__ mpack,
              __half* __restrict__ heads)
{
    extern __shared__ char smraw[];
    const uint32_t ksbase = smem_u32(smraw);
    const uint32_t vsbase = ksbase + KS_BYTES;

    const int bid = blockIdx.x;
    const int b = bid >> 5, h = (bid >> 2) & 7, qb = bid & 3;
    const int tid = threadIdx.x, lane = tid & 31, wid = tid >> 5;

    for (int i = tid; i < NN * 2; i += 256){
        int row = i >> 1, cc = i & 1;
        const __half* base = qkv + (size_t)(b * NN + row) * QKVN + h * DKK;
        *(uint4*)(smraw + row * 48 + cc * 16) = *(const uint4*)(base + DD + cc * 8);
        *(uint4*)(smraw + KS_BYTES + row * 48 + cc * 16) =
            *(const uint4*)(base + 2 * DD + cc * 8);
    }
    __syncthreads();

    const __half* Qb = qkv + (size_t)(b * NN) * QKVN + h * DKK;
    const int bfr = (lane & 7) + ((lane >> 4) << 3);
    const int bhi = (lane >> 3) & 1;
    const int vcol = (lane >> 4) << 4;
    const uint32_t bones = ((lane >> 2) == 0) ? 0x3C003C00u : 0u;

    const int qrow = qb * 128 + wid * 16 + (lane >> 2);

    uint32_t aq[4];
    {
        const __half* q0 = Qb + (size_t)qrow * QKVN + (lane & 3) * 2;
        const __half* q1 = Qb + (size_t)(qrow + 8) * QKVN + (lane & 3) * 2;
        aq[0] = *(const uint32_t*)q0;
        aq[1] = *(const uint32_t*)q1;
        aq[2] = *(const uint32_t*)(q0 + 8);
        aq[3] = *(const uint32_t*)(q1 + 8);
    }

    float m0 = MINIT, m1 = MINIT;
    float o[2][4], o2[4];
#pragma unroll
    for (int vt = 0; vt < 2; vt++)
#pragma unroll
        for (int i = 0; i < 4; i++) o[vt][i] = 0.f;
#pragma unroll
    for (int i = 0; i < 4; i++) o2[i] = 0.f;

    for (int kb = 0; kb < 8; kb++){
        float s[8][4];
#pragma unroll
        for (int nt = 0; nt < 8; nt++)
            s[nt][0] = s[nt][1] = s[nt][2] = s[nt][3] = 0.f;
#pragma unroll
        for (int pr = 0; pr < 4; pr++){
            int rn = kb * 64 + pr * 16 + bfr;
            uint32_t b0, b1, b2, b3;
            ldsm4(b0, b1, b2, b3, ksbase + rn * 48 + bhi * 16);
            mma_f16(s[2*pr],     aq, b0, b1);
            mma_f16(s[2*pr + 1], aq, b2, b3);
        }
        // mask (Q already carries SCL)
        const unsigned* mpr = mpack + ((size_t)(b * NN + qrow) << 4) + kb * 2;
        unsigned mw00 = mpr[0], mw01 = mpr[1];
        unsigned mw10 = mpr[8 * 16], mw11 = mpr[8 * 16 + 1];
#pragma unroll
        for (int nt = 0; nt < 8; nt++){
            int cb = nt * 8 + (lane & 3) * 2;
            unsigned wlo = (cb & 32) ? mw01 : mw00;
            unsigned whi = (cb & 32) ? mw11 : mw10;
            int bit = cb & 31;
            s[nt][0] = ((wlo >> bit)       & 1) ? s[nt][0] : MASKVAL;
            s[nt][1] = ((wlo >> (bit + 1)) & 1) ? s[nt][1] : MASKVAL;
            s[nt][2] = ((whi >> bit)       & 1) ? s[nt][2] : MASKVAL;
            s[nt][3] = ((whi >> (bit + 1)) & 1) ? s[nt][3] : MASKVAL;
        }
        // online softmax (log2 domain, hardware EX2)
        float rx0 = MASKVAL, rx1 = MASKVAL;
#pragma unroll
        for (int nt = 0; nt < 8; nt++){
            rx0 = fmaxf(rx0, fmaxf(s[nt][0], s[nt][1]));
            rx1 = fmaxf(rx1, fmaxf(s[nt][2], s[nt][3]));
        }
        rx0 = fmaxf(rx0, __shfl_xor_sync(0xffffffffu, rx0, 1));
        rx0 = fmaxf(rx0, __shfl_xor_sync(0xffffffffu, rx0, 2));
        rx1 = fmaxf(rx1, __shfl_xor_sync(0xffffffffu, rx1, 1));
        rx1 = fmaxf(rx1, __shfl_xor_sync(0xffffffffu, rx1, 2));
        float nm0 = fmaxf(m0, rx0), nm1 = fmaxf(m1, rx1);
        float f0 = ex2f(m0 - nm0), f1 = ex2f(m1 - nm1);
        m0 = nm0; m1 = nm1;
#pragma unroll
        for (int vt = 0; vt < 2; vt++){
            o[vt][0] *= f0; o[vt][1] *= f0;
            o[vt][2] *= f1; o[vt][3] *= f1;
        }
        o2[0] *= f0; o2[2] *= f1;
        // p = exp2(s - m) in packed fp16 (cvt saturates masked to -inf -> p=0)
        uint32_t pp[8][2];
#pragma unroll
        for (int nt = 0; nt < 8; nt++){
            pp[nt][0] = ex2h2(f16x2(s[nt][1] - m0, s[nt][0] - m0));
            pp[nt][1] = ex2h2(f16x2(s[nt][3] - m1, s[nt][2] - m1));
        }
        // P @ V  (+ ones-column row-sum mma for the denominator)
#pragma unroll
        for (int kt = 0; kt < 4; kt++){
            uint32_t pa[4];
            pa[0] = pp[2 * kt][0];
            pa[1] = pp[2 * kt][1];
            pa[2] = pp[2 * kt + 1][0];
            pa[3] = pp[2 * kt + 1][1];
            int rv = kb * 64 + kt * 16 + (lane & 15);
            uint32_t vb0, vb1, vb2, vb3;
            ldsm4t(vb0, vb1, vb2, vb3, vsbase + rv * 48 + vcol);
            mma_f16(o[0], pa, vb0, vb1);
            mma_f16(o[1], pa, vb2, vb3);
            mma_f16(o2, pa, bones, bones);
        }
    }

    // denominator: row sums live in col 0 of o2 (lane with lane%4==0)
    float l0 = __shfl_sync(0xffffffffu, o2[0], lane & ~3);
    float l1 = __shfl_sync(0xffffffffu, o2[2], lane & ~3);
    float i0 = 1.f / l0, i1 = 1.f / l1;
#pragma unroll
    for (int vt = 0; vt < 2; vt++){
        int col = h * DKK + vt * 8 + (lane & 3) * 2;
        *(__half2*)&heads[(size_t)(b * NN + qrow) * DD + col] =
            __floats2half2_rn(o[vt][0] * i0, o[vt][1] * i0);
        *(__half2*)&heads[(size_t)(b * NN + qrow + 8) * DD + col] =
            __floats2half2_rn(o[vt][2] * i1, o[vt][3] * i1);
    }
}

// ---------------- pooling + Wp ------------------------------------------------
__global__ void pool_kernel(const float* __restrict__ h, const float* __restrict__ Wp,
                            float* __restrict__ hpp)
{
    __shared__ float mean[DD];
    int b = blockIdx.x, d = threadIdx.x;
    const float* hp = h + (size_t)b * NN * DD + d;
    float s = 0.f;
    for (int n = 0; n < NN; n++) s += hp[(size_t)n * DD];
    mean[d] = s * (1.f / (float)NN);
    __syncthreads();
    float acc = 0.f;
#pragma unroll 4
    for (int i = 0; i < DD; i++) acc += mean[i] * Wp[i * DD + d];
    hpp[b * DD + d] = acc;
}

// ---------------- readout ----------------------------------------------------
__global__ void readout_kernel(const float* __restrict__ h, const float* __restrict__ hpp,
                               const float* __restrict__ Wr, const float* __restrict__ br,
                               float* __restrict__ out)
{
    __shared__ float WrS[2 * DD * OUTD];
    __shared__ float brS[OUTD];
    int tid = threadIdx.x;
    for (int i = tid; i < 2 * DD * OUTD; i += 128) WrS[i] = Wr[i];
    if (tid < OUTD) brS[tid] = br[tid];
    __syncthreads();

    int row = blockIdx.x * 128 + tid;
    int b = row >> 9;
    float a0 = brS[0], a1 = brS[1], a2 = brS[2];
    const float* hp = hpp + b * DD;
#pragma unroll 4
    for (int i = 0; i < DD; i++){
        float f = fmaxf(hp[i], 0.f);
        a0 += f * WrS[i * 3 + 0]; a1 += f * WrS[i * 3 + 1]; a2 += f * WrS[i * 3 + 2];
    }
    const float* hr = h + (size_t)row * DD;
#pragma unroll 4
    for (int i = 0; i < DD; i++){
        float f = fmaxf(hr[i], 0.f);
        a0 += f * WrS[(DD + i) * 3 + 0];
        a1 += f * WrS[(DD + i) * 3 + 1];
        a2 += f * WrS[(DD + i) * 3 + 2];
    }
    out[row * 3 + 0] = a0; out[row * 3 + 1] = a1; out[row * 3 + 2] = a2;
}

// ---------------- host launcher ----------------------------------------------
extern "C" void kernel_launch(void* const* d_in, const int* in_sizes, int n_in,
                              void* d_out, int out_size)
{
    const float* x    = (const float*)d_in[0];
    const int*   mask = (const int*)  d_in[1];
    const float* We   = (const float*)d_in[2];
    const float* Wq   = (const float*)d_in[3];
    const float* Wk   = (const float*)d_in[4];
    const float* Wv   = (const float*)d_in[5];
    const float* Wout = (const float*)d_in[6];
    const float* Wff1 = (const float*)d_in[7];
    const float* bff1 = (const float*)d_in[8];
    const float* Wff2 = (const float*)d_in[9];
    const float* bff2 = (const float*)d_in[10];
    const float* Wp   = (const float*)d_in[11];
    const float* Wr   = (const float*)d_in[12];
    const float* br   = (const float*)d_in[13];
    float* out = (float*)d_out;

    float *h, *hpp;
    __half *hh, *qkv, *heads, *ff, *xh, *weT, *wqkvT, *woutT, *wff1T, *wff2T;
    unsigned* mp;
    cudaGetSymbolAddress((void**)&h,     g_h);
    cudaGetSymbolAddress((void**)&hh,    g_hh);
    cudaGetSymbolAddress((void**)&qkv,   g_qkv);
    cudaGetSymbolAddress((void**)&heads, g_heads);
    cudaGetSymbolAddress((void**)&ff,    g_ff);
    cudaGetSymbolAddress((void**)&xh,    g_xh);
    cudaGetSymbolAddress((void**)&hpp,   g_hpp);
    cudaGetSymbolAddress((void**)&mp,    g_mpack);
    cudaGetSymbolAddress((void**)&weT,   g_weT);
    cudaGetSymbolAddress((void**)&wqkvT, g_wqkvT);
    cudaGetSymbolAddress((void**)&woutT, g_woutT);
    cudaGetSymbolAddress((void**)&wff1T, g_wff1T);
    cudaGetSymbolAddress((void**)&wff2T, g_wff2T);

    const int SM16 = 3 * (64*48 + 64*48);
    const int FK1  = FK_STAGE;
    const int FK4  = 2 * FK_STAGE;
    cudaFuncSetAttribute(gemm_hc<16>, cudaFuncAttributeMaxDynamicSharedMemorySize, SM16);
    cudaFuncSetAttribute(gemm_fk<1>, cudaFuncAttributeMaxDynamicSharedMemorySize, FK1);
    cudaFuncSetAttribute(gemm_fk<4>, cudaFuncAttributeMaxDynamicSharedMemorySize, FK4);
    cudaFuncSetAttribute(attn_mma, cudaFuncAttributeMaxDynamicSharedMemorySize, ATTN_SMEM);

    prep_all<<<(N_PREP + 255)/256, 256>>>(x, We, Wq, Wk, Wv, Wout, Wff1, Wff2, mask,
                                          xh, weT, wqkvT, woutT, wff1T, wff2T, mp);

    // embed: h = relu(x @ We), exact + fp16 copy (K=16)
    gemm_hc<16><<<dim3(DD/64, ROWS/64), 128, SM16>>>(
        xh, weT, nullptr, nullptr, h, hh, ROWS, FIN, DD, 1, 0);

    for (int l = 0; l < LYR; l++){
        // fused QKV (fp16 out; Q cols pre-scaled by SCL) — barrier-free K=128
        gemm_fk<1><<<dim3(QKVN/64, ROWS/128), 256, FK1>>>(
            hh, wqkvT + (size_t)l * QKVN * DD, nullptr, nullptr,
            nullptr, qkv, QKVN, 0, 1);

        // attention: 1 query-block of 128 per CTA
        attn_mma<<<BB * HH * 4, 256, ATTN_SMEM>>>(qkv, mp, heads);

        // h = h + heads @ Wout[l]  (exact + fp16) — barrier-free K=128
        gemm_fk<1><<<dim3(DD/64, ROWS/128), 256, FK1>>>(
            heads, woutT + (size_t)l * DD * DD, nullptr, h,
            h, hh, DD, 0, 0);

        // ff = relu(h @ Wff1 + bff1) — barrier-free K=128
        gemm_fk<1><<<dim3(FF/64, ROWS/128), 256, FK1>>>(
            hh, wff1T + (size_t)l * FF * DD, bff1 + (size_t)l * FF, nullptr,
            nullptr, ff, FF, 1, 0);

        // h = h + ff @ Wff2 + bff2 — K=512, 4 double-buffered chunks
        gemm_fk<4><<<dim3(DD/64, ROWS/128), 256, FK4>>>(
            ff, wff2T + (size_t)l * DD * FF, bff2 + (size_t)l * DD, h,
            h, hh, DD, 0, 0);
    }

    pool_kernel<<<BB, DD>>>(h, Wp, hpp);
    readout_kernel<<<ROWS/128, 128>>>(h, hpp, Wr, br, out);
}